// round 13
// baseline (speedup 1.0000x reference)
#include <cuda_runtime.h>
#include <cuda_bf16.h>
#include <cstdint>

#define Bb 4
#define Nn 256
#define Ee 256
#define Hh 16
#define Dd 16
#define FFh 512
#define Ll 5
#define BNE (Bb*Nn*Ee)          // 262144
#define BNF (Bb*Nn*FFh)         // 524288

// ================= device scratch =================
__device__ float g_scaled [Bb*Nn*Nn];
__device__ float g_scaledT[Bb*Nn*Nn];
__device__ float g_mnp[32], g_mxp[32];
__device__ float g_alpha[Ll*2*Hh], g_beta[Ll*2*Hh];
__device__ float g_qkv0u[3*2*256], g_qkv0v[3*2*256];   // rank-1 layer-0 QKV vectors
__device__ float g_bufA[2*BNE], g_bufB[2*BNE];
__device__ float g_Q[2*BNE], g_K[2*BNE], g_V[2*BNE];
__device__ float g_t1[2*BNE], g_o1[2*BNE];

__device__ __nv_bfloat16 g_xhA[2*BNE], g_xlA[2*BNE], g_xhB[2*BNE], g_xlB[2*BNE];
__device__ __nv_bfloat16 g_oh[2*BNE],  g_ol[2*BNE];
__device__ __nv_bfloat16 g_o1h[2*BNE], g_o1l[2*BNE];
__device__ __nv_bfloat16 g_ffh[2*BNF], g_ffl[2*BNF];
__device__ __nv_bfloat16 g_wqh[10*65536],  g_wql[10*65536];
__device__ __nv_bfloat16 g_wkh[10*65536],  g_wkl[10*65536];
__device__ __nv_bfloat16 g_wvh[10*65536],  g_wvl[10*65536];
__device__ __nv_bfloat16 g_wch[10*65536],  g_wcl[10*65536];
__device__ __nv_bfloat16 g_w1h[10*131072], g_w1l[10*131072];
__device__ __nv_bfloat16 g_w2h[10*131072], g_w2l[10*131072];

#if defined(__CUDA_ARCH__) && (__CUDA_ARCH__ >= 900)
#define PDL_SYNC()    cudaGridDependencySynchronize()
#define PDL_TRIGGER() cudaTriggerProgrammaticLaunchCompletion()
#else
#define PDL_SYNC()
#define PDL_TRIGGER()
#endif

// ================= setup kernels =================
__global__ void k_minmax(const float* __restrict__ data)
{
    PDL_SYNC();
    int b = blockIdx.x >> 3, seg = blockIdx.x & 7, tid = threadIdx.x;
    const float* p = data + (size_t)b*Nn*Nn + seg*8192;
    float lmn = 1e30f, lmx = -1e30f;
    #pragma unroll
    for (int i = 0; i < 32; i++){ float v = p[tid + i*256]; lmn = fminf(lmn,v); lmx = fmaxf(lmx,v); }
    __shared__ float smn[256], smx[256];
    smn[tid]=lmn; smx[tid]=lmx; __syncthreads();
    for (int s=128; s; s>>=1){ if (tid<s){ smn[tid]=fminf(smn[tid],smn[tid+s]); smx[tid]=fmaxf(smx[tid],smx[tid+s]); } __syncthreads(); }
    PDL_TRIGGER();
    if (!tid){ g_mnp[blockIdx.x]=smn[0]; g_mxp[blockIdx.x]=smx[0]; }
}

__global__ void k_scale(const float* __restrict__ data, float* __restrict__ S, float* __restrict__ ST)
{
    PDL_SYNC();
    int b = blockIdx.z;
    float m0v = 1e30f, M = -1e30f;
    #pragma unroll
    for (int j = 0; j < 8; j++){
        m0v = fminf(m0v, g_mnp[b*8+j]);
        M   = fmaxf(M,   g_mxp[b*8+j]);
    }
    float r = M - m0v; if (r == 0.f) r = 1.f;
    float inv = 1.f/r;
    __shared__ float tile[32][33];
    int n0 = blockIdx.y*32, mm0 = blockIdx.x*32;
    int tx = threadIdx.x, ty0 = threadIdx.y;
    #pragma unroll
    for (int i=0;i<4;i++){
        int ty = ty0 + i*8;
        float v = (data[((size_t)b*Nn + n0+ty)*Nn + mm0+tx] - m0v)*inv;
        S[((size_t)b*Nn + n0+ty)*Nn + mm0+tx] = v;
        tile[ty][tx] = v;
    }
    __syncthreads();
    PDL_TRIGGER();
    #pragma unroll
    for (int i=0;i<4;i++){
        int ty = ty0 + i*8;
        ST[((size_t)b*Nn + mm0+ty)*Nn + n0+tx] = tile[tx][ty];
    }
}

__global__ void k_ab(const float* __restrict__ Wedge, const float* __restrict__ bedge,
                     const float* __restrict__ Wmix)
{
    PDL_SYNC();
    int ij = blockIdx.x, h = blockIdx.y, lane = threadIdx.x;
    float a = 0.f, bb = 0.f;
    for (int e = lane; e < Ee; e += 32){
        float wm = Wmix[((size_t)ij*Ee + e)*Hh + h];
        a  += Wedge[e]*wm;
        bb += bedge[e]*wm;
    }
    for (int o=16;o;o>>=1){ a += __shfl_xor_sync(0xffffffffu,a,o); bb += __shfl_xor_sync(0xffffffffu,bb,o); }
    PDL_TRIGGER();
    if (!lane){ g_alpha[ij*Hh+h]=a; g_beta[ij*Hh+h]=bb; }
}

// rank-1 layer-0 QKV vectors: grid (3,2) [mat: 0=Q,1=K,2=V][z], 256 threads (one out col each)
__global__ void k_vec0(const float* __restrict__ Wnode, const float* __restrict__ bnode,
                       const float* __restrict__ Wq, const float* __restrict__ Wk,
                       const float* __restrict__ Wv)
{
    PDL_SYNC();
    int mat = blockIdx.x, z = blockIdx.y, j = threadIdx.x;
    const float* W = (mat==0 ? Wq : mat==1 ? Wk : Wv) + (size_t)z*Ee*256;
    float u = 0.f, v = 0.f;
    for (int e = 0; e < Ee; e++){
        float w = W[(size_t)e*256 + j];
        u = fmaf(Wnode[e], w, u);
        v = fmaf(bnode[e], w, v);
    }
    PDL_TRIGGER();
    g_qkv0u[(mat*2+z)*256 + j] = u;
    g_qkv0v[(mat*2+z)*256 + j] = v;
}

// emb + direct layer-0 Q/K/V (rank-1) — layer-0 xh/xl splits no longer needed
__global__ void k_emb(const float* __restrict__ nr, const float* __restrict__ Wn,
                      const float* __restrict__ bn)
{
    PDL_SYNC();
    int idx = blockIdx.x*256 + threadIdx.x;
    int e = idx & (Ee-1), bni = idx >> 8;
    float r = nr[bni];
    float v = r*Wn[e] + bn[e];
    g_bufA[idx] = v; g_bufA[idx + BNE] = v;
    #pragma unroll
    for (int z = 0; z < 2; z++){
        g_Q[(size_t)z*BNE + idx] = fmaf(r, g_qkv0u[(0*2+z)*256 + e], g_qkv0v[(0*2+z)*256 + e]);
        g_K[(size_t)z*BNE + idx] = fmaf(r, g_qkv0u[(1*2+z)*256 + e], g_qkv0v[(1*2+z)*256 + e]);
        g_V[(size_t)z*BNE + idx] = fmaf(r, g_qkv0u[(2*2+z)*256 + e], g_qkv0v[(2*2+z)*256 + e]);
    }
    PDL_TRIGGER();
}

__global__ void k_tsplit_all(
    const float* __restrict__ Wq, const float* __restrict__ Wk,
    const float* __restrict__ Wv, const float* __restrict__ Wc,
    const float* __restrict__ W1, const float* __restrict__ W2)
{
    PDL_SYNC();
    int bid = blockIdx.x;
    const float* s; __nv_bfloat16 *oh, *ol;
    int K, N, n0, k0, mat;
    if (bid < 2560){
        int type = bid / 640, loc = bid - type*640;
        mat = loc >> 6; int tile = loc & 63;
        if (type < 3 && mat < 2) return;          // layer-0 Wq/Wk/Wv unused (rank-1 path)
        K = 256; N = 256;
        n0 = (tile & 7)*32; k0 = (tile >> 3)*32;
        s  = (type==0?Wq:type==1?Wk:type==2?Wv:Wc);
        oh = (type==0?g_wqh:type==1?g_wkh:type==2?g_wvh:g_wch);
        ol = (type==0?g_wql:type==1?g_wkl:type==2?g_wvl:g_wcl);
    } else if (bid < 3840){
        int loc = bid - 2560;
        mat = loc >> 7; int tile = loc & 127;
        K = 256; N = 512;
        n0 = (tile & 15)*32; k0 = (tile >> 4)*32;
        s = W1; oh = g_w1h; ol = g_w1l;
    } else {
        int loc = bid - 3840;
        mat = loc >> 7; int tile = loc & 127;
        K = 512; N = 256;
        n0 = (tile & 7)*32; k0 = (tile >> 3)*32;
        s = W2; oh = g_w2h; ol = g_w2l;
    }
    s  += (size_t)mat*K*N;
    oh += (size_t)mat*K*N;
    ol += (size_t)mat*K*N;
    __shared__ float ts[32][33];
    int tx = threadIdx.x, ty = threadIdx.y;
    #pragma unroll
    for (int i=0;i<4;i++) ts[ty+i*8][tx] = s[(size_t)(k0+ty+i*8)*N + n0+tx];
    __syncthreads();
    PDL_TRIGGER();
    #pragma unroll
    for (int i=0;i<4;i++){
        int n = n0+ty+i*8, k = k0+tx;
        float v = ts[tx][ty+i*8];
        __nv_bfloat16 hi = __float2bfloat16(v);
        oh[(size_t)n*K + k] = hi;
        ol[(size_t)n*K + k] = __float2bfloat16(v - __bfloat162float(hi));
    }
}

// ================= HMMA 3xBF16 GEMM core, 2-stage cp.async (R10 proven) =================
__device__ __forceinline__ void cp16(uint32_t dst, const void* src){
    asm volatile("cp.async.cg.shared.global [%0], [%1], 16;\n" :: "r"(dst), "l"(src));
}
__device__ __forceinline__ void hmma(float* c, const uint32_t* a, const uint32_t* b){
    asm volatile("mma.sync.aligned.m16n8k16.row.col.f32.bf16.bf16.f32 "
        "{%0,%1,%2,%3}, {%4,%5,%6,%7}, {%8,%9}, {%0,%1,%2,%3};"
        : "+f"(c[0]), "+f"(c[1]), "+f"(c[2]), "+f"(c[3])
        : "r"(a[0]), "r"(a[1]), "r"(a[2]), "r"(a[3]), "r"(b[0]), "r"(b[1]));
}

__device__ __forceinline__ void tgemm_core(
    const __nv_bfloat16* __restrict__ ah, const __nv_bfloat16* __restrict__ al,
    const __nv_bfloat16* __restrict__ wh, const __nv_bfloat16* __restrict__ wl,
    const float* __restrict__ bias, const float* __restrict__ res,
    float* __restrict__ Cf, __nv_bfloat16* __restrict__ Chi, __nv_bfloat16* __restrict__ Clo,
    int m0, int n0, int Ng, int K, int relu)
{
    __shared__ __align__(16) __nv_bfloat16 smb[2][4][64*40];
    int tid = threadIdx.x;
    int lane = tid & 31, w = tid >> 5;
    int wm = (w >> 1)*32, wn = (w & 1)*32;
    int g = lane >> 2, tg = lane & 3;
    uint32_t sbase;
    asm("{ .reg .u64 t; cvta.to.shared.u64 t, %1; cvt.u32.u64 %0, t; }"
        : "=r"(sbase) : "l"((void*)&smb[0][0][0]));

    float acc[2][4][4];
    #pragma unroll
    for (int mi=0;mi<2;mi++)
        #pragma unroll
        for (int ni=0;ni<4;ni++)
            #pragma unroll
            for (int q=0;q<4;q++) acc[mi][ni][q]=0.f;

    const int nch = K >> 5;
    int crow = tid >> 2, cseg = (tid & 3)*8;

    auto issue = [&](int c){
        uint32_t sb2 = sbase + (uint32_t)((c & 1) ? 20480 : 0);
        int co = c*32 + cseg;
        #pragma unroll
        for (int it = 0; it < 2; it++){
            int row = crow + it*32;
            uint32_t dof = (uint32_t)((row*40 + cseg)*2);
            cp16(sb2         + dof, ah + (size_t)(m0+row)*K + co);
            cp16(sb2 + 5120  + dof, al + (size_t)(m0+row)*K + co);
            cp16(sb2 + 10240 + dof, wh + (size_t)(n0+row)*K + co);
            cp16(sb2 + 15360 + dof, wl + (size_t)(n0+row)*K + co);
        }
        asm volatile("cp.async.commit_group;\n");
    };

    issue(0);
    for (int c = 0; c < nch; c++){
        asm volatile("cp.async.wait_group 0;\n");
        __syncthreads();
        if (c + 1 < nch) issue(c + 1);
        int st = c & 1;
        const __nv_bfloat16* pA0 = &smb[st][0][0];
        const __nv_bfloat16* pA1 = &smb[st][1][0];
        const __nv_bfloat16* pB0 = &smb[st][2][0];
        const __nv_bfloat16* pB1 = &smb[st][3][0];
        #pragma unroll
        for (int ks = 0; ks < 2; ks++){
            int kb = ks*16 + 2*tg;
            uint32_t fah[2][4], fal[2][4];
            #pragma unroll
            for (int mi = 0; mi < 2; mi++){
                int rb = wm + mi*16 + g;
                fah[mi][0] = *(const uint32_t*)&pA0[rb*40 + kb];
                fah[mi][1] = *(const uint32_t*)&pA0[(rb+8)*40 + kb];
                fah[mi][2] = *(const uint32_t*)&pA0[rb*40 + kb + 8];
                fah[mi][3] = *(const uint32_t*)&pA0[(rb+8)*40 + kb + 8];
                fal[mi][0] = *(const uint32_t*)&pA1[rb*40 + kb];
                fal[mi][1] = *(const uint32_t*)&pA1[(rb+8)*40 + kb];
                fal[mi][2] = *(const uint32_t*)&pA1[rb*40 + kb + 8];
                fal[mi][3] = *(const uint32_t*)&pA1[(rb+8)*40 + kb + 8];
            }
            uint32_t fbh[4][2], fbl[4][2];
            #pragma unroll
            for (int ni = 0; ni < 4; ni++){
                int nb = wn + ni*8 + g;
                fbh[ni][0] = *(const uint32_t*)&pB0[nb*40 + kb];
                fbh[ni][1] = *(const uint32_t*)&pB0[nb*40 + kb + 8];
                fbl[ni][0] = *(const uint32_t*)&pB1[nb*40 + kb];
                fbl[ni][1] = *(const uint32_t*)&pB1[nb*40 + kb + 8];
            }
            #pragma unroll
            for (int mi = 0; mi < 2; mi++)
                #pragma unroll
                for (int ni = 0; ni < 4; ni++){
                    hmma(acc[mi][ni], fah[mi], fbh[ni]);
                    hmma(acc[mi][ni], fah[mi], fbl[ni]);
                    hmma(acc[mi][ni], fal[mi], fbh[ni]);
                }
        }
    }

    PDL_TRIGGER();
    #pragma unroll
    for (int mi = 0; mi < 2; mi++){
        #pragma unroll
        for (int ni = 0; ni < 4; ni++){
            int col = n0 + wn + ni*8 + 2*tg;
            float b0 = bias ? bias[col]   : 0.f;
            float b1 = bias ? bias[col+1] : 0.f;
            #pragma unroll
            for (int half = 0; half < 2; half++){
                int m = m0 + wm + mi*16 + g + half*8;
                float v0 = acc[mi][ni][half*2+0] + b0;
                float v1 = acc[mi][ni][half*2+1] + b1;
                if (res){
                    v0 += res[(size_t)m*Ng + col];
                    v1 += res[(size_t)m*Ng + col+1];
                }
                if (relu){ v0 = fmaxf(v0, 0.f); v1 = fmaxf(v1, 0.f); }
                if (Cf){
                    float2 o; o.x = v0; o.y = v1;
                    *(float2*)&Cf[(size_t)m*Ng + col] = o;
                }
                if (Chi){
                    __nv_bfloat16 h0 = __float2bfloat16(v0), h1 = __float2bfloat16(v1);
                    __nv_bfloat162 hp; hp.x = h0; hp.y = h1;
                    __nv_bfloat162 lp;
                    lp.x = __float2bfloat16(v0 - __bfloat162float(h0));
                    lp.y = __float2bfloat16(v1 - __bfloat162float(h1));
                    *(__nv_bfloat162*)&Chi[(size_t)m*Ng + col] = hp;
                    *(__nv_bfloat162*)&Clo[(size_t)m*Ng + col] = lp;
                }
            }
        }
    }
}

// fused QKV: grid (12, 16, 2)
__global__ void __launch_bounds__(128) k_tqkv(
                       const __nv_bfloat16* __restrict__ xh, const __nv_bfloat16* __restrict__ xl,
                       const __nv_bfloat16* wqh, const __nv_bfloat16* wql,
                       const __nv_bfloat16* wkh, const __nv_bfloat16* wkl,
                       const __nv_bfloat16* wvh, const __nv_bfloat16* wvl,
                       float* Q, float* K, float* V)
{
    PDL_SYNC();
    int wsel = blockIdx.x >> 2, nt = blockIdx.x & 3, z = blockIdx.z;
    int az = wsel ? (1 - z) : z;
    const __nv_bfloat16 *wh, *wl; float* out;
    if (wsel == 0){ wh = wqh; wl = wql; out = Q; }
    else if (wsel == 1){ wh = wkh; wl = wkl; out = K; }
    else { wh = wvh; wl = wvl; out = V; }
    tgemm_core(xh + (size_t)az*BNE, xl + (size_t)az*BNE,
               wh + (size_t)z*65536, wl + (size_t)z*65536,
               nullptr, nullptr,
               out + (size_t)z*BNE, nullptr, nullptr,
               blockIdx.y*64, nt*64, 256, 256, 0);
}

__global__ void __launch_bounds__(128) k_tgemm(
                        const __nv_bfloat16* __restrict__ ah, const __nv_bfloat16* __restrict__ al, int aStrideZ,
                        const __nv_bfloat16* __restrict__ wh, const __nv_bfloat16* __restrict__ wl, int wStrideZ,
                        const float* bias, int biasStrideZ,
                        const float* res, int resStrideZ,
                        float* Cf, __nv_bfloat16* Chi, __nv_bfloat16* Clo, int cStrideZ,
                        int Ng, int K, int relu)
{
    PDL_SYNC();
    int z = blockIdx.z;
    tgemm_core(ah + (size_t)z*aStrideZ, al + (size_t)z*aStrideZ,
               wh + (size_t)z*wStrideZ, wl + (size_t)z*wStrideZ,
               bias ? bias + (size_t)z*biasStrideZ : nullptr,
               res  ? res  + (size_t)z*resStrideZ  : nullptr,
               Cf  ? Cf  + (size_t)z*cStrideZ : nullptr,
               Chi ? Chi + (size_t)z*cStrideZ : nullptr,
               Clo ? Clo + (size_t)z*cStrideZ : nullptr,
               blockIdx.y*64, blockIdx.x*64, Ng, K, relu);
}

// ================= fused attention: 2 row-groups per block =================
__global__ void __launch_bounds__(256) k_attn(
    const float* __restrict__ Q, const float* __restrict__ Kg, const float* __restrict__ Vg,
    const float* __restrict__ scaled, const float* __restrict__ scaledT,
    const float* __restrict__ alpha, const float* __restrict__ beta,
    __nv_bfloat16* __restrict__ Oh, __nv_bfloat16* __restrict__ Ol)
{
    PDL_SYNC();
    __shared__ float qs[32][17];
    __shared__ float Vs[256][17];
    __shared__ float Ks[256][17];
    __shared__ float red[4][545];
    __shared__ float sminv[32];

    int rgp = blockIdx.x, bh = blockIdx.y, z = blockIdx.z;
    int b = bh >> 4, h = bh & 15;
    const float* Sc = z ? scaledT : scaled;
    size_t base = ((size_t)(z*Bb+b))*(size_t)Nn*Ee;
    const float* Kp = Kg + base + h*16;
    const float* Vp = Vg + base + h*16;
    float al = alpha[z*Hh+h], be = beta[z*Hh+h];
    int tid = threadIdx.x;

    {
        int m = tid, sh = m >> 4;
        const float4* kr4 = (const float4*)(Kp + (size_t)m*Ee);
        const float4* vr4 = (const float4*)(Vp + (size_t)m*Ee);
        #pragma unroll
        for (int j4 = 0; j4 < 4; j4++){
            float4 kv = kr4[j4], vv = vr4[j4];
            Ks[m][(j4*4+0+sh)&15] = kv.x;
            Ks[m][(j4*4+1+sh)&15] = kv.y;
            Ks[m][(j4*4+2+sh)&15] = kv.z;
            Ks[m][(j4*4+3+sh)&15] = kv.w;
            Vs[m][(j4*4+0+sh)&15] = vv.x;
            Vs[m][(j4*4+1+sh)&15] = vv.y;
            Vs[m][(j4*4+2+sh)&15] = vv.z;
            Vs[m][(j4*4+3+sh)&15] = vv.w;
        }
    }

    int n2 = tid >> 4, s16 = tid & 15, m0 = s16*16;

    #pragma unroll
    for (int pass = 0; pass < 2; pass++){
        int rg = rgp*2 + pass;
        __syncthreads();
        {
            int r = tid >> 3, dq = (tid & 7)*2;
            const float* Qp = Q + base + (size_t)(rg*32 + r)*Ee + h*16;
            float2 q2 = *(const float2*)(Qp + dq);
            qs[r][dq]   = q2.x*0.25f;
            qs[r][dq+1] = q2.y*0.25f;
        }
        __syncthreads();

        float q0[16], q1[16];
        #pragma unroll
        for (int d = 0; d < 16; d++){ q0[d] = qs[n2][d]; q1[d] = qs[n2+16][d]; }

        float acc0[16], acc1[16];
        {
            const float* sr0 = Sc + ((size_t)b*Nn + rg*32 + n2)*Nn + m0;
            const float* sr1 = sr0 + (size_t)16*Nn;
            #pragma unroll
            for (int j = 0; j < 16; j += 4){
                float4 v0 = *(const float4*)&sr0[j];
                acc0[j]   = fmaf(v0.x, al, be); acc0[j+1] = fmaf(v0.y, al, be);
                acc0[j+2] = fmaf(v0.z, al, be); acc0[j+3] = fmaf(v0.w, al, be);
                float4 v1 = *(const float4*)&sr1[j];
                acc1[j]   = fmaf(v1.x, al, be); acc1[j+1] = fmaf(v1.y, al, be);
                acc1[j+2] = fmaf(v1.z, al, be); acc1[j+3] = fmaf(v1.w, al, be);
            }
        }
        #pragma unroll
        for (int j = 0; j < 16; j++){
            const float* kr = &Ks[m0+j][0];
            float a0 = acc0[j], a1 = acc1[j];
            #pragma unroll
            for (int d = 0; d < 16; d++){
                float kv = kr[(d+s16)&15];
                a0 = fmaf(q0[d], kv, a0);
                a1 = fmaf(q1[d], kv, a1);
            }
            acc0[j] = a0; acc1[j] = a1;
        }

        float mx0 = -1e30f, mx1 = -1e30f;
        #pragma unroll
        for (int j = 0; j < 16; j++){ mx0 = fmaxf(mx0, acc0[j]); mx1 = fmaxf(mx1, acc1[j]); }
        #pragma unroll
        for (int o = 1; o < 16; o <<= 1){
            mx0 = fmaxf(mx0, __shfl_xor_sync(0xffffffffu, mx0, o));
            mx1 = fmaxf(mx1, __shfl_xor_sync(0xffffffffu, mx1, o));
        }
        float sm0 = 0.f, sm1 = 0.f;
        #pragma unroll
        for (int j = 0; j < 16; j++){
            acc0[j] = __expf(acc0[j]-mx0); sm0 += acc0[j];
            acc1[j] = __expf(acc1[j]-mx1); sm1 += acc1[j];
        }
        #pragma unroll
        for (int o = 1; o < 16; o <<= 1){
            sm0 += __shfl_xor_sync(0xffffffffu, sm0, o);
            sm1 += __shfl_xor_sync(0xffffffffu, sm1, o);
        }
        if (s16 == 0){ sminv[n2] = 1.f/sm0; sminv[n2+16] = 1.f/sm1; }

        float p0[16], p1[16];
        #pragma unroll
        for (int d = 0; d < 16; d++){ p0[d] = 0.f; p1[d] = 0.f; }
        #pragma unroll
        for (int j = 0; j < 16; j++){
            const float* vr = &Vs[m0+j][0];
            float e0 = acc0[j], e1 = acc1[j];
            #pragma unroll
            for (int d = 0; d < 16; d++){
                float vv = vr[(d+s16)&15];
                p0[d] = fmaf(e0, vv, p0[d]);
                p1[d] = fmaf(e1, vv, p1[d]);
            }
        }
        #pragma unroll
        for (int d = 0; d < 16; d++){
            p0[d] += __shfl_xor_sync(0xffffffffu, p0[d], 8);
            p1[d] += __shfl_xor_sync(0xffffffffu, p1[d], 8);
            p0[d] += __shfl_xor_sync(0xffffffffu, p0[d], 4);
            p1[d] += __shfl_xor_sync(0xffffffffu, p1[d], 4);
        }
        if (s16 < 4){
            #pragma unroll
            for (int d = 0; d < 16; d++){
                red[s16][n2*17 + d]      = p0[d];
                red[s16][(n2+16)*17 + d] = p1[d];
            }
        }
        __syncthreads();

        if (pass == 1){ PDL_TRIGGER(); }
        {
            int r = tid >> 3, dp = (tid & 7)*2;
            float s0 = 0.f, s1 = 0.f;
            #pragma unroll
            for (int s = 0; s < 4; s++){
                s0 += red[s][r*17 + dp];
                s1 += red[s][r*17 + dp + 1];
            }
            float iv = sminv[r];
            float v0 = s0*iv, v1 = s1*iv;
            size_t off = base + (size_t)(rg*32 + r)*Ee + h*16 + dp;
            __nv_bfloat16 h0 = __float2bfloat16(v0), h1 = __float2bfloat16(v1);
            __nv_bfloat162 hp; hp.x = h0; hp.y = h1;
            __nv_bfloat162 lp;
            lp.x = __float2bfloat16(v0 - __bfloat162float(h0));
            lp.y = __float2bfloat16(v1 - __bfloat162float(h1));
            *(__nv_bfloat162*)&Oh[off] = hp;
            *(__nv_bfloat162*)&Ol[off] = lp;
        }
    }
}

// instance norm + optional bf16 split; grid (Bb, 16, 2), 256 thr
__global__ void __launch_bounds__(256) k_inorm(
                        const float* __restrict__ X, float* __restrict__ Y,
                        const float* __restrict__ wbase, const float* __restrict__ bbase,
                        __nv_bfloat16* __restrict__ Yh, __nv_bfloat16* __restrict__ Yl)
{
    PDL_SYNC();
    int z = blockIdx.z, b = blockIdx.x, e0 = blockIdx.y*16;
    const float* w = wbase + (size_t)z*Ee;
    const float* bp = bbase + (size_t)z*Ee;
    int tid = threadIdx.x;
    int el = tid & 15, nc = tid >> 4;
    size_t base = ((size_t)(z*Bb+b))*Nn*Ee;
    float vals[16];
    float s = 0.f, ss = 0.f;
    #pragma unroll
    for (int k = 0; k < 16; k++){
        float v = X[base + (size_t)(nc + 16*k)*Ee + e0 + el];
        vals[k] = v;
        s += v; ss += v*v;
    }
    __shared__ float shs[16][17], shss[16][17];
    __shared__ float muA[16], invA[16];
    shs[nc][el] = s; shss[nc][el] = ss;
    __syncthreads();
    if (tid < 16){
        float S = 0.f, SS = 0.f;
        #pragma unroll
        for (int j = 0; j < 16; j++){ S += shs[j][tid]; SS += shss[j][tid]; }
        float mu = S*(1.f/Nn);
        float var = SS*(1.f/Nn) - mu*mu;
        muA[tid] = mu;
        invA[tid] = rsqrtf(var + 1e-5f);
    }
    __syncthreads();
    float mu = muA[el];
    float sc = invA[el]*w[e0+el];
    float sb = bp[e0+el];
    PDL_TRIGGER();
    #pragma unroll
    for (int k = 0; k < 16; k++){
        size_t off = base + (size_t)(nc + 16*k)*Ee + e0 + el;
        float y = (vals[k]-mu)*sc + sb;
        Y[off] = y;
        if (Yh){
            __nv_bfloat16 hi = __float2bfloat16(y);
            Yh[off] = hi;
            Yl[off] = __float2bfloat16(y - __bfloat162float(hi));
        }
    }
}

// ================= host launcher =================
template <typename F, typename... A>
static inline void pdl_launch(F f, dim3 grid, dim3 block, A... args)
{
    cudaLaunchConfig_t cfg = {};
    cfg.gridDim = grid; cfg.blockDim = block;
    cfg.dynamicSmemBytes = 0; cfg.stream = 0;
    cudaLaunchAttribute at[1];
    at[0].id = cudaLaunchAttributeProgrammaticStreamSerialization;
    at[0].val.programmaticStreamSerializationAllowed = 1;
    cfg.attrs = at; cfg.numAttrs = 1;
    if (cudaLaunchKernelEx(&cfg, f, args...) != cudaSuccess)
        f<<<grid, block>>>(args...);
}

extern "C" void kernel_launch(void* const* d_in, const int* in_sizes, int n_in,
                              void* d_out, int out_size)
{
    const float* data      = (const float*)d_in[0];
    const float* node_rand = (const float*)d_in[1];
    const float* Wnode = (const float*)d_in[2];
    const float* bnode = (const float*)d_in[3];
    const float* Wedge = (const float*)d_in[4];
    const float* bedge = (const float*)d_in[5];
    const float* Wq    = (const float*)d_in[6];
    const float* Wk    = (const float*)d_in[7];
    const float* Wv    = (const float*)d_in[8];
    const float* Wcomb = (const float*)d_in[9];
    const float* bcomb = (const float*)d_in[10];
    const float* n1w   = (const float*)d_in[11];
    const float* n1b   = (const float*)d_in[12];
    const float* W1    = (const float*)d_in[13];
    const float* b1    = (const float*)d_in[14];
    const float* W2    = (const float*)d_in[15];
    const float* b2    = (const float*)d_in[16];
    const float* n2w   = (const float*)d_in[17];
    const float* n2b   = (const float*)d_in[18];
    const float* Wmix  = (const float*)d_in[19];

    float *scaled, *scaledT, *alpha, *beta;
    float *bufA, *bufB, *Qb, *Kb, *Vb, *t1, *o1;
    __nv_bfloat16 *xhA,*xlA,*xhB,*xlB,*oh,*ol,*o1h,*o1l,*ffh,*ffl;
    __nv_bfloat16 *wqh,*wql,*wkh,*wkl,*wvh,*wvl,*wch,*wcl,*w1h,*w1l,*w2h,*w2l;
    cudaGetSymbolAddress((void**)&scaled,  g_scaled);
    cudaGetSymbolAddress((void**)&scaledT, g_scaledT);
    cudaGetSymbolAddress((void**)&alpha,   g_alpha);
    cudaGetSymbolAddress((void**)&beta,    g_beta);
    cudaGetSymbolAddress((void**)&bufA,    g_bufA);
    cudaGetSymbolAddress((void**)&bufB,    g_bufB);
    cudaGetSymbolAddress((void**)&Qb,      g_Q);
    cudaGetSymbolAddress((void**)&Kb,      g_K);
    cudaGetSymbolAddress((void**)&Vb,      g_V);
    cudaGetSymbolAddress((void**)&t1,      g_t1);
    cudaGetSymbolAddress((void**)&o1,      g_o1);
    cudaGetSymbolAddress((void**)&xhA, g_xhA); cudaGetSymbolAddress((void**)&xlA, g_xlA);
    cudaGetSymbolAddress((void**)&xhB, g_xhB); cudaGetSymbolAddress((void**)&xlB, g_xlB);
    cudaGetSymbolAddress((void**)&oh,  g_oh);  cudaGetSymbolAddress((void**)&ol,  g_ol);
    cudaGetSymbolAddress((void**)&o1h, g_o1h); cudaGetSymbolAddress((void**)&o1l, g_o1l);
    cudaGetSymbolAddress((void**)&ffh, g_ffh); cudaGetSymbolAddress((void**)&ffl, g_ffl);
    cudaGetSymbolAddress((void**)&wqh, g_wqh); cudaGetSymbolAddress((void**)&wql, g_wql);
    cudaGetSymbolAddress((void**)&wkh, g_wkh); cudaGetSymbolAddress((void**)&wkl, g_wkl);
    cudaGetSymbolAddress((void**)&wvh, g_wvh); cudaGetSymbolAddress((void**)&wvl, g_wvl);
    cudaGetSymbolAddress((void**)&wch, g_wch); cudaGetSymbolAddress((void**)&wcl, g_wcl);
    cudaGetSymbolAddress((void**)&w1h, g_w1h); cudaGetSymbolAddress((void**)&w1l, g_w1l);
    cudaGetSymbolAddress((void**)&w2h, g_w2h); cudaGetSymbolAddress((void**)&w2l, g_w2l);

    // setup
    pdl_launch(k_minmax, dim3(32), dim3(256), data);
    pdl_launch(k_scale, dim3(8,8,Bb), dim3(32,8), data, scaled, scaledT);
    pdl_launch(k_ab, dim3(Ll*2, Hh), dim3(32), Wedge, bedge, Wmix);
    pdl_launch(k_vec0, dim3(3,2), dim3(256), Wnode, bnode, Wq, Wk, Wv);
    pdl_launch(k_emb, dim3(BNE/256), dim3(256), node_rand, Wnode, bnode);
    pdl_launch(k_tsplit_all, dim3(5120), dim3(32,8), Wq, Wk, Wv, Wcomb, W1, W2);

    for (int i = 0; i < Ll; i++){
        const float* Xc = (i & 1) ? bufB : bufA;
        __nv_bfloat16* xhc = (i & 1) ? xhB : xhA;
        __nv_bfloat16* xlc = (i & 1) ? xlB : xlA;
        __nv_bfloat16* xhn = (i & 1) ? xhA : xhB;
        __nv_bfloat16* xln = (i & 1) ? xlA : xlB;
        int last = (i == Ll-1);
        float* Xn = last ? (float*)d_out : ((i & 1) ? bufA : bufB);
        size_t w256 = (size_t)i*2*65536;
        size_t w512 = (size_t)i*2*131072;
        const float* bcomb_i = bcomb + (size_t)i*2*Ee;
        const float* b1_i    = b1    + (size_t)i*2*FFh;
        const float* b2_i    = b2    + (size_t)i*2*Ee;

        if (i > 0){   // layer 0 Q/K/V produced directly by k_emb (rank-1)
            pdl_launch(k_tqkv, dim3(12,16,2), dim3(128),
                (const __nv_bfloat16*)xhc, (const __nv_bfloat16*)xlc,
                (const __nv_bfloat16*)(wqh + w256), (const __nv_bfloat16*)(wql + w256),
                (const __nv_bfloat16*)(wkh + w256), (const __nv_bfloat16*)(wkl + w256),
                (const __nv_bfloat16*)(wvh + w256), (const __nv_bfloat16*)(wvl + w256),
                Qb, Kb, Vb);
        }
        pdl_launch(k_attn, dim3(4, Bb*Hh, 2), dim3(256),
            (const float*)Qb, (const float*)Kb, (const float*)Vb,
            (const float*)scaled, (const float*)scaledT,
            (const float*)(alpha + i*2*Hh), (const float*)(beta + i*2*Hh), oh, ol);
        pdl_launch(k_tgemm, dim3(4,16,2), dim3(128),
            (const __nv_bfloat16*)oh, (const __nv_bfloat16*)ol, (int)BNE,
            (const __nv_bfloat16*)(wch + w256), (const __nv_bfloat16*)(wcl + w256), (int)65536,
            bcomb_i, (int)Ee, (const float*)Xc, (int)BNE,
            t1, (__nv_bfloat16*)nullptr, (__nv_bfloat16*)nullptr, (int)BNE, (int)256, (int)256, (int)0);
        pdl_launch(k_inorm, dim3(Bb,16,2), dim3(256),
            (const float*)t1, o1, n1w + (size_t)i*2*Ee, n1b + (size_t)i*2*Ee, o1h, o1l);
        pdl_launch(k_tgemm, dim3(8,16,2), dim3(128),
            (const __nv_bfloat16*)o1h, (const __nv_bfloat16*)o1l, (int)BNE,
            (const __nv_bfloat16*)(w1h + w512), (const __nv_bfloat16*)(w1l + w512), (int)131072,
            b1_i, (int)FFh, (const float*)nullptr, (int)0,
            (float*)nullptr, ffh, ffl, (int)BNF, (int)512, (int)256, (int)1);
        pdl_launch(k_tgemm, dim3(4,16,2), dim3(128),
            (const __nv_bfloat16*)ffh, (const __nv_bfloat16*)ffl, (int)BNF,
            (const __nv_bfloat16*)(w2h + w512), (const __nv_bfloat16*)(w2l + w512), (int)131072,
            b2_i, (int)Ee, (const float*)o1, (int)BNE,
            t1, (__nv_bfloat16*)nullptr, (__nv_bfloat16*)nullptr, (int)BNE, (int)256, (int)512, (int)0);
        pdl_launch(k_inorm, dim3(Bb,16,2), dim3(256),
            (const float*)t1, Xn, n2w + (size_t)i*2*Ee, n2b + (size_t)i*2*Ee,
            last ? (__nv_bfloat16*)nullptr : xhn, last ? (__nv_bfloat16*)nullptr : xln);
    }
}

// round 15
// speedup vs baseline: 1.0355x; 1.0355x over previous
#include <cuda_runtime.h>
#include <cuda_bf16.h>
#include <cstdint>

#define Bb 4
#define Nn 256
#define Ee 256
#define Hh 16
#define Dd 16
#define FFh 512
#define Ll 5
#define BNE (Bb*Nn*Ee)          // 262144
#define BNF (Bb*Nn*FFh)         // 524288

// ================= device scratch =================
__device__ float g_scaled [Bb*Nn*Nn];
__device__ float g_scaledT[Bb*Nn*Nn];
__device__ float g_mnp[32], g_mxp[32];
__device__ float g_alpha[Ll*2*Hh], g_beta[Ll*2*Hh];
__device__ float g_p0u[6*16*256], g_p0v[6*16*256];     // vec0 partials
__device__ float g_qkv0u[3*2*256], g_qkv0v[3*2*256];   // rank-1 layer-0 QKV vectors
__device__ float g_bufA[2*BNE], g_bufB[2*BNE];
__device__ float g_Q[2*BNE], g_K[2*BNE], g_V[2*BNE];
__device__ float g_t1[2*BNE], g_o1[2*BNE];

__device__ __nv_bfloat16 g_xhA[2*BNE], g_xlA[2*BNE], g_xhB[2*BNE], g_xlB[2*BNE];
__device__ __nv_bfloat16 g_oh[2*BNE],  g_ol[2*BNE];
__device__ __nv_bfloat16 g_o1h[2*BNE], g_o1l[2*BNE];
__device__ __nv_bfloat16 g_ffh[2*BNF], g_ffl[2*BNF];
__device__ __nv_bfloat16 g_wqh[10*65536],  g_wql[10*65536];
__device__ __nv_bfloat16 g_wkh[10*65536],  g_wkl[10*65536];
__device__ __nv_bfloat16 g_wvh[10*65536],  g_wvl[10*65536];
__device__ __nv_bfloat16 g_wch[10*65536],  g_wcl[10*65536];
__device__ __nv_bfloat16 g_w1h[10*131072], g_w1l[10*131072];
__device__ __nv_bfloat16 g_w2h[10*131072], g_w2l[10*131072];

#if defined(__CUDA_ARCH__) && (__CUDA_ARCH__ >= 900)
#define PDL_SYNC()    cudaGridDependencySynchronize()
#define PDL_TRIGGER() cudaTriggerProgrammaticLaunchCompletion()
#else
#define PDL_SYNC()
#define PDL_TRIGGER()
#endif

// ================= setup kernels =================
__global__ void k_minmax(const float* __restrict__ data)
{
    PDL_SYNC();
    int b = blockIdx.x >> 3, seg = blockIdx.x & 7, tid = threadIdx.x;
    const float* p = data + (size_t)b*Nn*Nn + seg*8192;
    float lmn = 1e30f, lmx = -1e30f;
    #pragma unroll
    for (int i = 0; i < 32; i++){ float v = p[tid + i*256]; lmn = fminf(lmn,v); lmx = fmaxf(lmx,v); }
    __shared__ float smn[256], smx[256];
    smn[tid]=lmn; smx[tid]=lmx; __syncthreads();
    for (int s=128; s; s>>=1){ if (tid<s){ smn[tid]=fminf(smn[tid],smn[tid+s]); smx[tid]=fmaxf(smx[tid],smx[tid+s]); } __syncthreads(); }
    PDL_TRIGGER();
    if (!tid){ g_mnp[blockIdx.x]=smn[0]; g_mxp[blockIdx.x]=smx[0]; }
}

__global__ void k_scale(const float* __restrict__ data, float* __restrict__ S, float* __restrict__ ST)
{
    PDL_SYNC();
    int b = blockIdx.z;
    float m0v = 1e30f, M = -1e30f;
    #pragma unroll
    for (int j = 0; j < 8; j++){
        m0v = fminf(m0v, g_mnp[b*8+j]);
        M   = fmaxf(M,   g_mxp[b*8+j]);
    }
    float r = M - m0v; if (r == 0.f) r = 1.f;
    float inv = 1.f/r;
    __shared__ float tile[32][33];
    int n0 = blockIdx.y*32, mm0 = blockIdx.x*32;
    int tx = threadIdx.x, ty0 = threadIdx.y;
    #pragma unroll
    for (int i=0;i<4;i++){
        int ty = ty0 + i*8;
        float v = (data[((size_t)b*Nn + n0+ty)*Nn + mm0+tx] - m0v)*inv;
        S[((size_t)b*Nn + n0+ty)*Nn + mm0+tx] = v;
        tile[ty][tx] = v;
    }
    __syncthreads();
    PDL_TRIGGER();
    #pragma unroll
    for (int i=0;i<4;i++){
        int ty = ty0 + i*8;
        ST[((size_t)b*Nn + mm0+ty)*Nn + n0+tx] = tile[tx][ty];
    }
}

__global__ void k_ab(const float* __restrict__ Wedge, const float* __restrict__ bedge,
                     const float* __restrict__ Wmix)
{
    PDL_SYNC();
    int ij = blockIdx.x, h = blockIdx.y, lane = threadIdx.x;
    float a = 0.f, bb = 0.f;
    for (int e = lane; e < Ee; e += 32){
        float wm = Wmix[((size_t)ij*Ee + e)*Hh + h];
        a  += Wedge[e]*wm;
        bb += bedge[e]*wm;
    }
    for (int o=16;o;o>>=1){ a += __shfl_xor_sync(0xffffffffu,a,o); bb += __shfl_xor_sync(0xffffffffu,bb,o); }
    PDL_TRIGGER();
    if (!lane){ g_alpha[ij*Hh+h]=a; g_beta[ij*Hh+h]=bb; }
}

// vec0 stage A: grid (6,16); block (mat*2+z, seg) reduces 16 e-rows for all 256 j
__global__ void k_vec0a(const float* __restrict__ Wnode, const float* __restrict__ bnode,
                        const float* __restrict__ Wq, const float* __restrict__ Wk,
                        const float* __restrict__ Wv)
{
    PDL_SYNC();
    int idx = blockIdx.x, seg = blockIdx.y, j = threadIdx.x;
    int mat = idx >> 1, z = idx & 1;
    const float* W = (mat==0 ? Wq : mat==1 ? Wk : Wv) + (size_t)z*Ee*256 + (size_t)seg*16*256 + j;
    int e0 = seg*16;
    float u = 0.f, v = 0.f;
    #pragma unroll
    for (int e = 0; e < 16; e++){
        float w = W[e*256];
        u = fmaf(Wnode[e0+e], w, u);
        v = fmaf(bnode[e0+e], w, v);
    }
    PDL_TRIGGER();
    g_p0u[(idx*16 + seg)*256 + j] = u;
    g_p0v[(idx*16 + seg)*256 + j] = v;
}

// vec0 stage B: grid 6; fold 16 partials
__global__ void k_vec0b()
{
    PDL_SYNC();
    int idx = blockIdx.x, j = threadIdx.x;
    float u = 0.f, v = 0.f;
    #pragma unroll
    for (int s = 0; s < 16; s++){
        u += g_p0u[(idx*16 + s)*256 + j];
        v += g_p0v[(idx*16 + s)*256 + j];
    }
    PDL_TRIGGER();
    g_qkv0u[idx*256 + j] = u;
    g_qkv0v[idx*256 + j] = v;
}

// emb + direct layer-0 Q/K/V (rank-1)
__global__ void k_emb(const float* __restrict__ nr, const float* __restrict__ Wn,
                      const float* __restrict__ bn)
{
    PDL_SYNC();
    int idx = blockIdx.x*256 + threadIdx.x;
    int e = idx & (Ee-1), bni = idx >> 8;
    float r = nr[bni];
    float v = r*Wn[e] + bn[e];
    g_bufA[idx] = v; g_bufA[idx + BNE] = v;
    #pragma unroll
    for (int z = 0; z < 2; z++){
        g_Q[(size_t)z*BNE + idx] = fmaf(r, g_qkv0u[(0*2+z)*256 + e], g_qkv0v[(0*2+z)*256 + e]);
        g_K[(size_t)z*BNE + idx] = fmaf(r, g_qkv0u[(1*2+z)*256 + e], g_qkv0v[(1*2+z)*256 + e]);
        g_V[(size_t)z*BNE + idx] = fmaf(r, g_qkv0u[(2*2+z)*256 + e], g_qkv0v[(2*2+z)*256 + e]);
    }
    PDL_TRIGGER();
}

__global__ void k_tsplit_all(
    const float* __restrict__ Wq, const float* __restrict__ Wk,
    const float* __restrict__ Wv, const float* __restrict__ Wc,
    const float* __restrict__ W1, const float* __restrict__ W2)
{
    PDL_SYNC();
    int bid = blockIdx.x;
    const float* s; __nv_bfloat16 *oh, *ol;
    int K, N, n0, k0, mat;
    if (bid < 2560){
        int type = bid / 640, loc = bid - type*640;
        mat = loc >> 6; int tile = loc & 63;
        if (type < 3 && mat < 2) return;          // layer-0 Wq/Wk/Wv unused (rank-1 path)
        K = 256; N = 256;
        n0 = (tile & 7)*32; k0 = (tile >> 3)*32;
        s  = (type==0?Wq:type==1?Wk:type==2?Wv:Wc);
        oh = (type==0?g_wqh:type==1?g_wkh:type==2?g_wvh:g_wch);
        ol = (type==0?g_wql:type==1?g_wkl:type==2?g_wvl:g_wcl);
    } else if (bid < 3840){
        int loc = bid - 2560;
        mat = loc >> 7; int tile = loc & 127;
        K = 256; N = 512;
        n0 = (tile & 15)*32; k0 = (tile >> 4)*32;
        s = W1; oh = g_w1h; ol = g_w1l;
    } else {
        int loc = bid - 3840;
        mat = loc >> 7; int tile = loc & 127;
        K = 512; N = 256;
        n0 = (tile & 7)*32; k0 = (tile >> 3)*32;
        s = W2; oh = g_w2h; ol = g_w2l;
    }
    s  += (size_t)mat*K*N;
    oh += (size_t)mat*K*N;
    ol += (size_t)mat*K*N;
    __shared__ float ts[32][33];
    int tx = threadIdx.x, ty = threadIdx.y;
    #pragma unroll
    for (int i=0;i<4;i++) ts[ty+i*8][tx] = s[(size_t)(k0+ty+i*8)*N + n0+tx];
    __syncthreads();
    PDL_TRIGGER();
    #pragma unroll
    for (int i=0;i<4;i++){
        int n = n0+ty+i*8, k = k0+tx;
        float v = ts[tx][ty+i*8];
        __nv_bfloat16 hi = __float2bfloat16(v);
        oh[(size_t)n*K + k] = hi;
        ol[(size_t)n*K + k] = __float2bfloat16(v - __bfloat162float(hi));
    }
}

// ================= HMMA 3xBF16 GEMM core, 2-stage cp.async =================
__device__ __forceinline__ void cp16(uint32_t dst, const void* src){
    asm volatile("cp.async.cg.shared.global [%0], [%1], 16;\n" :: "r"(dst), "l"(src));
}
__device__ __forceinline__ void hmma(float* c, const uint32_t* a, const uint32_t* b){
    asm volatile("mma.sync.aligned.m16n8k16.row.col.f32.bf16.bf16.f32 "
        "{%0,%1,%2,%3}, {%4,%5,%6,%7}, {%8,%9}, {%0,%1,%2,%3};"
        : "+f"(c[0]), "+f"(c[1]), "+f"(c[2]), "+f"(c[3])
        : "r"(a[0]), "r"(a[1]), "r"(a[2]), "r"(a[3]), "r"(b[0]), "r"(b[1]));
}

__device__ __forceinline__ void tgemm_core(
    const __nv_bfloat16* __restrict__ ah, const __nv_bfloat16* __restrict__ al,
    const __nv_bfloat16* __restrict__ wh, const __nv_bfloat16* __restrict__ wl,
    const float* __restrict__ bias, const float* __restrict__ res,
    float* __restrict__ Cf, __nv_bfloat16* __restrict__ Chi, __nv_bfloat16* __restrict__ Clo,
    int m0, int n0, int Ng, int K, int relu)
{
    __shared__ __align__(16) __nv_bfloat16 smb[2][4][64*40];
    int tid = threadIdx.x;
    int lane = tid & 31, w = tid >> 5;
    int wm = (w >> 1)*32, wn = (w & 1)*32;
    int g = lane >> 2, tg = lane & 3;
    uint32_t sbase;
    asm("{ .reg .u64 t; cvta.to.shared.u64 t, %1; cvt.u32.u64 %0, t; }"
        : "=r"(sbase) : "l"((void*)&smb[0][0][0]));

    float acc[2][4][4];
    #pragma unroll
    for (int mi=0;mi<2;mi++)
        #pragma unroll
        for (int ni=0;ni<4;ni++)
            #pragma unroll
            for (int q=0;q<4;q++) acc[mi][ni][q]=0.f;

    const int nch = K >> 5;
    int crow = tid >> 2, cseg = (tid & 3)*8;

    auto issue = [&](int c){
        uint32_t sb2 = sbase + (uint32_t)((c & 1) ? 20480 : 0);
        int co = c*32 + cseg;
        #pragma unroll
        for (int it = 0; it < 2; it++){
            int row = crow + it*32;
            uint32_t dof = (uint32_t)((row*40 + cseg)*2);
            cp16(sb2         + dof, ah + (size_t)(m0+row)*K + co);
            cp16(sb2 + 5120  + dof, al + (size_t)(m0+row)*K + co);
            cp16(sb2 + 10240 + dof, wh + (size_t)(n0+row)*K + co);
            cp16(sb2 + 15360 + dof, wl + (size_t)(n0+row)*K + co);
        }
        asm volatile("cp.async.commit_group;\n");
    };

    issue(0);
    for (int c = 0; c < nch; c++){
        asm volatile("cp.async.wait_group 0;\n");
        __syncthreads();
        if (c + 1 < nch) issue(c + 1);
        int st = c & 1;
        const __nv_bfloat16* pA0 = &smb[st][0][0];
        const __nv_bfloat16* pA1 = &smb[st][1][0];
        const __nv_bfloat16* pB0 = &smb[st][2][0];
        const __nv_bfloat16* pB1 = &smb[st][3][0];
        #pragma unroll
        for (int ks = 0; ks < 2; ks++){
            int kb = ks*16 + 2*tg;
            uint32_t fah[2][4], fal[2][4];
            #pragma unroll
            for (int mi = 0; mi < 2; mi++){
                int rb = wm + mi*16 + g;
                fah[mi][0] = *(const uint32_t*)&pA0[rb*40 + kb];
                fah[mi][1] = *(const uint32_t*)&pA0[(rb+8)*40 + kb];
                fah[mi][2] = *(const uint32_t*)&pA0[rb*40 + kb + 8];
                fah[mi][3] = *(const uint32_t*)&pA0[(rb+8)*40 + kb + 8];
                fal[mi][0] = *(const uint32_t*)&pA1[rb*40 + kb];
                fal[mi][1] = *(const uint32_t*)&pA1[(rb+8)*40 + kb];
                fal[mi][2] = *(const uint32_t*)&pA1[rb*40 + kb + 8];
                fal[mi][3] = *(const uint32_t*)&pA1[(rb+8)*40 + kb + 8];
            }
            uint32_t fbh[4][2], fbl[4][2];
            #pragma unroll
            for (int ni = 0; ni < 4; ni++){
                int nb = wn + ni*8 + g;
                fbh[ni][0] = *(const uint32_t*)&pB0[nb*40 + kb];
                fbh[ni][1] = *(const uint32_t*)&pB0[nb*40 + kb + 8];
                fbl[ni][0] = *(const uint32_t*)&pB1[nb*40 + kb];
                fbl[ni][1] = *(const uint32_t*)&pB1[nb*40 + kb + 8];
            }
            #pragma unroll
            for (int mi = 0; mi < 2; mi++)
                #pragma unroll
                for (int ni = 0; ni < 4; ni++){
                    hmma(acc[mi][ni], fah[mi], fbh[ni]);
                    hmma(acc[mi][ni], fah[mi], fbl[ni]);
                    hmma(acc[mi][ni], fal[mi], fbh[ni]);
                }
        }
    }

    PDL_TRIGGER();
    #pragma unroll
    for (int mi = 0; mi < 2; mi++){
        #pragma unroll
        for (int ni = 0; ni < 4; ni++){
            int col = n0 + wn + ni*8 + 2*tg;
            float b0 = bias ? bias[col]   : 0.f;
            float b1 = bias ? bias[col+1] : 0.f;
            #pragma unroll
            for (int half = 0; half < 2; half++){
                int m = m0 + wm + mi*16 + g + half*8;
                float v0 = acc[mi][ni][half*2+0] + b0;
                float v1 = acc[mi][ni][half*2+1] + b1;
                if (res){
                    v0 += res[(size_t)m*Ng + col];
                    v1 += res[(size_t)m*Ng + col+1];
                }
                if (relu){ v0 = fmaxf(v0, 0.f); v1 = fmaxf(v1, 0.f); }
                if (Cf){
                    float2 o; o.x = v0; o.y = v1;
                    *(float2*)&Cf[(size_t)m*Ng + col] = o;
                }
                if (Chi){
                    __nv_bfloat16 h0 = __float2bfloat16(v0), h1 = __float2bfloat16(v1);
                    __nv_bfloat162 hp; hp.x = h0; hp.y = h1;
                    __nv_bfloat162 lp;
                    lp.x = __float2bfloat16(v0 - __bfloat162float(h0));
                    lp.y = __float2bfloat16(v1 - __bfloat162float(h1));
                    *(__nv_bfloat162*)&Chi[(size_t)m*Ng + col] = hp;
                    *(__nv_bfloat162*)&Clo[(size_t)m*Ng + col] = lp;
                }
            }
        }
    }
}

// fused QKV: grid (12, 16, 2)
__global__ void __launch_bounds__(128) k_tqkv(
                       const __nv_bfloat16* __restrict__ xh, const __nv_bfloat16* __restrict__ xl,
                       const __nv_bfloat16* wqh, const __nv_bfloat16* wql,
                       const __nv_bfloat16* wkh, const __nv_bfloat16* wkl,
                       const __nv_bfloat16* wvh, const __nv_bfloat16* wvl,
                       float* Q, float* K, float* V)
{
    PDL_SYNC();
    int wsel = blockIdx.x >> 2, nt = blockIdx.x & 3, z = blockIdx.z;
    int az = wsel ? (1 - z) : z;
    const __nv_bfloat16 *wh, *wl; float* out;
    if (wsel == 0){ wh = wqh; wl = wql; out = Q; }
    else if (wsel == 1){ wh = wkh; wl = wkl; out = K; }
    else { wh = wvh; wl = wvl; out = V; }
    tgemm_core(xh + (size_t)az*BNE, xl + (size_t)az*BNE,
               wh + (size_t)z*65536, wl + (size_t)z*65536,
               nullptr, nullptr,
               out + (size_t)z*BNE, nullptr, nullptr,
               blockIdx.y*64, nt*64, 256, 256, 0);
}

__global__ void __launch_bounds__(128) k_tgemm(
                        const __nv_bfloat16* __restrict__ ah, const __nv_bfloat16* __restrict__ al, int aStrideZ,
                        const __nv_bfloat16* __restrict__ wh, const __nv_bfloat16* __restrict__ wl, int wStrideZ,
                        const float* bias, int biasStrideZ,
                        const float* res, int resStrideZ,
                        float* Cf, __nv_bfloat16* Chi, __nv_bfloat16* Clo, int cStrideZ,
                        int Ng, int K, int relu)
{
    PDL_SYNC();
    int z = blockIdx.z;
    tgemm_core(ah + (size_t)z*aStrideZ, al + (size_t)z*aStrideZ,
               wh + (size_t)z*wStrideZ, wl + (size_t)z*wStrideZ,
               bias ? bias + (size_t)z*biasStrideZ : nullptr,
               res  ? res  + (size_t)z*resStrideZ  : nullptr,
               Cf  ? Cf  + (size_t)z*cStrideZ : nullptr,
               Chi ? Chi + (size_t)z*cStrideZ : nullptr,
               Clo ? Clo + (size_t)z*cStrideZ : nullptr,
               blockIdx.y*64, blockIdx.x*64, Ng, K, relu);
}

// ================= fused attention: 2 row-groups per block =================
__global__ void __launch_bounds__(256) k_attn(
    const float* __restrict__ Q, const float* __restrict__ Kg, const float* __restrict__ Vg,
    const float* __restrict__ scaled, const float* __restrict__ scaledT,
    const float* __restrict__ alpha, const float* __restrict__ beta,
    __nv_bfloat16* __restrict__ Oh, __nv_bfloat16* __restrict__ Ol)
{
    PDL_SYNC();
    __shared__ float qs[32][17];
    __shared__ float Vs[256][17];
    __shared__ float Ks[256][17];
    __shared__ float red[4][545];
    __shared__ float sminv[32];

    int rgp = blockIdx.x, bh = blockIdx.y, z = blockIdx.z;
    int b = bh >> 4, h = bh & 15;
    const float* Sc = z ? scaledT : scaled;
    size_t base = ((size_t)(z*Bb+b))*(size_t)Nn*Ee;
    const float* Kp = Kg + base + h*16;
    const float* Vp = Vg + base + h*16;
    float al = alpha[z*Hh+h], be = beta[z*Hh+h];
    int tid = threadIdx.x;

    {
        int m = tid, sh = m >> 4;
        const float4* kr4 = (const float4*)(Kp + (size_t)m*Ee);
        const float4* vr4 = (const float4*)(Vp + (size_t)m*Ee);
        #pragma unroll
        for (int j4 = 0; j4 < 4; j4++){
            float4 kv = kr4[j4], vv = vr4[j4];
            Ks[m][(j4*4+0+sh)&15] = kv.x;
            Ks[m][(j4*4+1+sh)&15] = kv.y;
            Ks[m][(j4*4+2+sh)&15] = kv.z;
            Ks[m][(j4*4+3+sh)&15] = kv.w;
            Vs[m][(j4*4+0+sh)&15] = vv.x;
            Vs[m][(j4*4+1+sh)&15] = vv.y;
            Vs[m][(j4*4+2+sh)&15] = vv.z;
            Vs[m][(j4*4+3+sh)&15] = vv.w;
        }
    }

    int n2 = tid >> 4, s16 = tid & 15, m0 = s16*16;

    #pragma unroll
    for (int pass = 0; pass < 2; pass++){
        int rg = rgp*2 + pass;
        __syncthreads();
        {
            int r = tid >> 3, dq = (tid & 7)*2;
            const float* Qp = Q + base + (size_t)(rg*32 + r)*Ee + h*16;
            float2 q2 = *(const float2*)(Qp + dq);
            qs[r][dq]   = q2.x*0.25f;
            qs[r][dq+1] = q2.y*0.25f;
        }
        __syncthreads();

        float q0[16], q1[16];
        #pragma unroll
        for (int d = 0; d < 16; d++){ q0[d] = qs[n2][d]; q1[d] = qs[n2+16][d]; }

        float acc0[16], acc1[16];
        {
            const float* sr0 = Sc + ((size_t)b*Nn + rg*32 + n2)*Nn + m0;
            const float* sr1 = sr0 + (size_t)16*Nn;
            #pragma unroll
            for (int j = 0; j < 16; j += 4){
                float4 v0 = *(const float4*)&sr0[j];
                acc0[j]   = fmaf(v0.x, al, be); acc0[j+1] = fmaf(v0.y, al, be);
                acc0[j+2] = fmaf(v0.z, al, be); acc0[j+3] = fmaf(v0.w, al, be);
                float4 v1 = *(const float4*)&sr1[j];
                acc1[j]   = fmaf(v1.x, al, be); acc1[j+1] = fmaf(v1.y, al, be);
                acc1[j+2] = fmaf(v1.z, al, be); acc1[j+3] = fmaf(v1.w, al, be);
            }
        }
        #pragma unroll
        for (int j = 0; j < 16; j++){
            const float* kr = &Ks[m0+j][0];
            float a0 = acc0[j], a1 = acc1[j];
            #pragma unroll
            for (int d = 0; d < 16; d++){
                float kv = kr[(d+s16)&15];
                a0 = fmaf(q0[d], kv, a0);
                a1 = fmaf(q1[d], kv, a1);
            }
            acc0[j] = a0; acc1[j] = a1;
        }

        float mx0 = -1e30f, mx1 = -1e30f;
        #pragma unroll
        for (int j = 0; j < 16; j++){ mx0 = fmaxf(mx0, acc0[j]); mx1 = fmaxf(mx1, acc1[j]); }
        #pragma unroll
        for (int o = 1; o < 16; o <<= 1){
            mx0 = fmaxf(mx0, __shfl_xor_sync(0xffffffffu, mx0, o));
            mx1 = fmaxf(mx1, __shfl_xor_sync(0xffffffffu, mx1, o));
        }
        float sm0 = 0.f, sm1 = 0.f;
        #pragma unroll
        for (int j = 0; j < 16; j++){
            acc0[j] = __expf(acc0[j]-mx0); sm0 += acc0[j];
            acc1[j] = __expf(acc1[j]-mx1); sm1 += acc1[j];
        }
        #pragma unroll
        for (int o = 1; o < 16; o <<= 1){
            sm0 += __shfl_xor_sync(0xffffffffu, sm0, o);
            sm1 += __shfl_xor_sync(0xffffffffu, sm1, o);
        }
        if (s16 == 0){ sminv[n2] = 1.f/sm0; sminv[n2+16] = 1.f/sm1; }

        float p0[16], p1[16];
        #pragma unroll
        for (int d = 0; d < 16; d++){ p0[d] = 0.f; p1[d] = 0.f; }
        #pragma unroll
        for (int j = 0; j < 16; j++){
            const float* vr = &Vs[m0+j][0];
            float e0 = acc0[j], e1 = acc1[j];
            #pragma unroll
            for (int d = 0; d < 16; d++){
                float vv = vr[(d+s16)&15];
                p0[d] = fmaf(e0, vv, p0[d]);
                p1[d] = fmaf(e1, vv, p1[d]);
            }
        }
        #pragma unroll
        for (int d = 0; d < 16; d++){
            p0[d] += __shfl_xor_sync(0xffffffffu, p0[d], 8);
            p1[d] += __shfl_xor_sync(0xffffffffu, p1[d], 8);
            p0[d] += __shfl_xor_sync(0xffffffffu, p0[d], 4);
            p1[d] += __shfl_xor_sync(0xffffffffu, p1[d], 4);
        }
        if (s16 < 4){
            #pragma unroll
            for (int d = 0; d < 16; d++){
                red[s16][n2*17 + d]      = p0[d];
                red[s16][(n2+16)*17 + d] = p1[d];
            }
        }
        __syncthreads();

        if (pass == 1){ PDL_TRIGGER(); }
        {
            int r = tid >> 3, dp = (tid & 7)*2;
            float s0 = 0.f, s1 = 0.f;
            #pragma unroll
            for (int s = 0; s < 4; s++){
                s0 += red[s][r*17 + dp];
                s1 += red[s][r*17 + dp + 1];
            }
            float iv = sminv[r];
            float v0 = s0*iv, v1 = s1*iv;
            size_t off = base + (size_t)(rg*32 + r)*Ee + h*16 + dp;
            __nv_bfloat16 h0 = __float2bfloat16(v0), h1 = __float2bfloat16(v1);
            __nv_bfloat162 hp; hp.x = h0; hp.y = h1;
            __nv_bfloat162 lp;
            lp.x = __float2bfloat16(v0 - __bfloat162float(h0));
            lp.y = __float2bfloat16(v1 - __bfloat162float(h1));
            *(__nv_bfloat162*)&Oh[off] = hp;
            *(__nv_bfloat162*)&Ol[off] = lp;
        }
    }
}

// instance norm + optional bf16 split; grid (Bb, 16, 2), 256 thr
__global__ void __launch_bounds__(256) k_inorm(
                        const float* __restrict__ X, float* __restrict__ Y,
                        const float* __restrict__ wbase, const float* __restrict__ bbase,
                        __nv_bfloat16* __restrict__ Yh, __nv_bfloat16* __restrict__ Yl)
{
    PDL_SYNC();
    int z = blockIdx.z, b = blockIdx.x, e0 = blockIdx.y*16;
    const float* w = wbase + (size_t)z*Ee;
    const float* bp = bbase + (size_t)z*Ee;
    int tid = threadIdx.x;
    int el = tid & 15, nc = tid >> 4;
    size_t base = ((size_t)(z*Bb+b))*Nn*Ee;
    float vals[16];
    float s = 0.f, ss = 0.f;
    #pragma unroll
    for (int k = 0; k < 16; k++){
        float v = X[base + (size_t)(nc + 16*k)*Ee + e0 + el];
        vals[k] = v;
        s += v; ss += v*v;
    }
    __shared__ float shs[16][17], shss[16][17];
    __shared__ float muA[16], invA[16];
    shs[nc][el] = s; shss[nc][el] = ss;
    __syncthreads();
    if (tid < 16){
        float S = 0.f, SS = 0.f;
        #pragma unroll
        for (int j = 0; j < 16; j++){ S += shs[j][tid]; SS += shss[j][tid]; }
        float mu = S*(1.f/Nn);
        float var = SS*(1.f/Nn) - mu*mu;
        muA[tid] = mu;
        invA[tid] = rsqrtf(var + 1e-5f);
    }
    __syncthreads();
    float mu = muA[el];
    float sc = invA[el]*w[e0+el];
    float sb = bp[e0+el];
    PDL_TRIGGER();
    #pragma unroll
    for (int k = 0; k < 16; k++){
        size_t off = base + (size_t)(nc + 16*k)*Ee + e0 + el;
        float y = (vals[k]-mu)*sc + sb;
        Y[off] = y;
        if (Yh){
            __nv_bfloat16 hi = __float2bfloat16(y);
            Yh[off] = hi;
            Yl[off] = __float2bfloat16(y - __bfloat162float(hi));
        }
    }
}

// ================= host launcher =================
template <typename F, typename... A>
static inline void pdl_launch(F f, dim3 grid, dim3 block, A... args)
{
    cudaLaunchConfig_t cfg = {};
    cfg.gridDim = grid; cfg.blockDim = block;
    cfg.dynamicSmemBytes = 0; cfg.stream = 0;
    cudaLaunchAttribute at[1];
    at[0].id = cudaLaunchAttributeProgrammaticStreamSerialization;
    at[0].val.programmaticStreamSerializationAllowed = 1;
    cfg.attrs = at; cfg.numAttrs = 1;
    if (cudaLaunchKernelEx(&cfg, f, args...) != cudaSuccess)
        f<<<grid, block>>>(args...);
}

extern "C" void kernel_launch(void* const* d_in, const int* in_sizes, int n_in,
                              void* d_out, int out_size)
{
    const float* data      = (const float*)d_in[0];
    const float* node_rand = (const float*)d_in[1];
    const float* Wnode = (const float*)d_in[2];
    const float* bnode = (const float*)d_in[3];
    const float* Wedge = (const float*)d_in[4];
    const float* bedge = (const float*)d_in[5];
    const float* Wq    = (const float*)d_in[6];
    const float* Wk    = (const float*)d_in[7];
    const float* Wv    = (const float*)d_in[8];
    const float* Wcomb = (const float*)d_in[9];
    const float* bcomb = (const float*)d_in[10];
    const float* n1w   = (const float*)d_in[11];
    const float* n1b   = (const float*)d_in[12];
    const float* W1    = (const float*)d_in[13];
    const float* b1    = (const float*)d_in[14];
    const float* W2    = (const float*)d_in[15];
    const float* b2    = (const float*)d_in[16];
    const float* n2w   = (const float*)d_in[17];
    const float* n2b   = (const float*)d_in[18];
    const float* Wmix  = (const float*)d_in[19];

    float *scaled, *scaledT, *alpha, *beta;
    float *bufA, *bufB, *Qb, *Kb, *Vb, *t1, *o1;
    __nv_bfloat16 *xhA,*xlA,*xhB,*xlB,*oh,*ol,*o1h,*o1l,*ffh,*ffl;
    __nv_bfloat16 *wqh,*wql,*wkh,*wkl,*wvh,*wvl,*wch,*wcl,*w1h,*w1l,*w2h,*w2l;
    cudaGetSymbolAddress((void**)&scaled,  g_scaled);
    cudaGetSymbolAddress((void**)&scaledT, g_scaledT);
    cudaGetSymbolAddress((void**)&alpha,   g_alpha);
    cudaGetSymbolAddress((void**)&beta,    g_beta);
    cudaGetSymbolAddress((void**)&bufA,    g_bufA);
    cudaGetSymbolAddress((void**)&bufB,    g_bufB);
    cudaGetSymbolAddress((void**)&Qb,      g_Q);
    cudaGetSymbolAddress((void**)&Kb,      g_K);
    cudaGetSymbolAddress((void**)&Vb,      g_V);
    cudaGetSymbolAddress((void**)&t1,      g_t1);
    cudaGetSymbolAddress((void**)&o1,      g_o1);
    cudaGetSymbolAddress((void**)&xhA, g_xhA); cudaGetSymbolAddress((void**)&xlA, g_xlA);
    cudaGetSymbolAddress((void**)&xhB, g_xhB); cudaGetSymbolAddress((void**)&xlB, g_xlB);
    cudaGetSymbolAddress((void**)&oh,  g_oh);  cudaGetSymbolAddress((void**)&ol,  g_ol);
    cudaGetSymbolAddress((void**)&o1h, g_o1h); cudaGetSymbolAddress((void**)&o1l, g_o1l);
    cudaGetSymbolAddress((void**)&ffh, g_ffh); cudaGetSymbolAddress((void**)&ffl, g_ffl);
    cudaGetSymbolAddress((void**)&wqh, g_wqh); cudaGetSymbolAddress((void**)&wql, g_wql);
    cudaGetSymbolAddress((void**)&wkh, g_wkh); cudaGetSymbolAddress((void**)&wkl, g_wkl);
    cudaGetSymbolAddress((void**)&wvh, g_wvh); cudaGetSymbolAddress((void**)&wvl, g_wvl);
    cudaGetSymbolAddress((void**)&wch, g_wch); cudaGetSymbolAddress((void**)&wcl, g_wcl);
    cudaGetSymbolAddress((void**)&w1h, g_w1h); cudaGetSymbolAddress((void**)&w1l, g_w1l);
    cudaGetSymbolAddress((void**)&w2h, g_w2h); cudaGetSymbolAddress((void**)&w2l, g_w2l);

    // setup
    pdl_launch(k_minmax, dim3(32), dim3(256), data);
    pdl_launch(k_scale, dim3(8,8,Bb), dim3(32,8), data, scaled, scaledT);
    pdl_launch(k_ab, dim3(Ll*2, Hh), dim3(32), Wedge, bedge, Wmix);
    pdl_launch(k_vec0a, dim3(6,16), dim3(256), Wnode, bnode, Wq, Wk, Wv);
    pdl_launch(k_vec0b, dim3(6), dim3(256));
    pdl_launch(k_emb, dim3(BNE/256), dim3(256), node_rand, Wnode, bnode);
    pdl_launch(k_tsplit_all, dim3(5120), dim3(32,8), Wq, Wk, Wv, Wcomb, W1, W2);

    for (int i = 0; i < Ll; i++){
        const float* Xc = (i & 1) ? bufB : bufA;
        __nv_bfloat16* xhc = (i & 1) ? xhB : xhA;
        __nv_bfloat16* xlc = (i & 1) ? xlB : xlA;
        __nv_bfloat16* xhn = (i & 1) ? xhA : xhB;
        __nv_bfloat16* xln = (i & 1) ? xlA : xlB;
        int last = (i == Ll-1);
        float* Xn = last ? (float*)d_out : ((i & 1) ? bufA : bufB);
        size_t w256 = (size_t)i*2*65536;
        size_t w512 = (size_t)i*2*131072;
        const float* bcomb_i = bcomb + (size_t)i*2*Ee;
        const float* b1_i    = b1    + (size_t)i*2*FFh;
        const float* b2_i    = b2    + (size_t)i*2*Ee;

        if (i > 0){   // layer 0 Q/K/V produced directly by k_emb (rank-1)
            pdl_launch(k_tqkv, dim3(12,16,2), dim3(128),
                (const __nv_bfloat16*)xhc, (const __nv_bfloat16*)xlc,
                (const __nv_bfloat16*)(wqh + w256), (const __nv_bfloat16*)(wql + w256),
                (const __nv_bfloat16*)(wkh + w256), (const __nv_bfloat16*)(wkl + w256),
                (const __nv_bfloat16*)(wvh + w256), (const __nv_bfloat16*)(wvl + w256),
                Qb, Kb, Vb);
        }
        pdl_launch(k_attn, dim3(4, Bb*Hh, 2), dim3(256),
            (const float*)Qb, (const float*)Kb, (const float*)Vb,
            (const float*)scaled, (const float*)scaledT,
            (const float*)(alpha + i*2*Hh), (const float*)(beta + i*2*Hh), oh, ol);
        pdl_launch(k_tgemm, dim3(4,16,2), dim3(128),
            (const __nv_bfloat16*)oh, (const __nv_bfloat16*)ol, (int)BNE,
            (const __nv_bfloat16*)(wch + w256), (const __nv_bfloat16*)(wcl + w256), (int)65536,
            bcomb_i, (int)Ee, (const float*)Xc, (int)BNE,
            t1, (__nv_bfloat16*)nullptr, (__nv_bfloat16*)nullptr, (int)BNE, (int)256, (int)256, (int)0);
        pdl_launch(k_inorm, dim3(Bb,16,2), dim3(256),
            (const float*)t1, o1, n1w + (size_t)i*2*Ee, n1b + (size_t)i*2*Ee, o1h, o1l);
        pdl_launch(k_tgemm, dim3(8,16,2), dim3(128),
            (const __nv_bfloat16*)o1h, (const __nv_bfloat16*)o1l, (int)BNE,
            (const __nv_bfloat16*)(w1h + w512), (const __nv_bfloat16*)(w1l + w512), (int)131072,
            b1_i, (int)FFh, (const float*)nullptr, (int)0,
            (float*)nullptr, ffh, ffl, (int)BNF, (int)512, (int)256, (int)1);
        pdl_launch(k_tgemm, dim3(4,16,2), dim3(128),
            (const __nv_bfloat16*)ffh, (const __nv_bfloat16*)ffl, (int)BNF,
            (const __nv_bfloat16*)(w2h + w512), (const __nv_bfloat16*)(w2l + w512), (int)131072,
            b2_i, (int)Ee, (const float*)o1, (int)BNE,
            t1, (__nv_bfloat16*)nullptr, (__nv_bfloat16*)nullptr, (int)BNE, (int)256, (int)512, (int)0);
        pdl_launch(k_inorm, dim3(Bb,16,2), dim3(256),
            (const float*)t1, Xn, n2w + (size_t)i*2*Ee, n2b + (size_t)i*2*Ee,
            last ? (__nv_bfloat16*)nullptr : xhn, last ? (__nv_bfloat16*)nullptr : xln);
    }
}

// round 16
// speedup vs baseline: 1.0597x; 1.0234x over previous
#include <cuda_runtime.h>
#include <cuda_bf16.h>
#include <cstdint>

#define Bb 4
#define Nn 256
#define Ee 256
#define Hh 16
#define Dd 16
#define FFh 512
#define Ll 5
#define BNE (Bb*Nn*Ee)          // 262144
#define BNF (Bb*Nn*FFh)         // 524288

// ================= device scratch =================
__device__ float g_scaled [Bb*Nn*Nn];
__device__ float g_scaledT[Bb*Nn*Nn];
__device__ float g_mnp[32], g_mxp[32];
__device__ float g_alpha[Ll*2*Hh], g_beta[Ll*2*Hh];
__device__ float g_p0u[6*16*256], g_p0v[6*16*256];     // vec0 partials
__device__ float g_qkv0u[3*2*256], g_qkv0v[3*2*256];   // rank-1 layer-0 QKV vectors
__device__ float g_bufA[2*BNE], g_bufB[2*BNE];
__device__ float g_Q[2*BNE], g_K[2*BNE], g_V[2*BNE];
__device__ float g_t1[2*BNE], g_o1[2*BNE];

__device__ __nv_bfloat16 g_xhA[2*BNE], g_xlA[2*BNE], g_xhB[2*BNE], g_xlB[2*BNE];
__device__ __nv_bfloat16 g_oh[2*BNE],  g_ol[2*BNE];
__device__ __nv_bfloat16 g_o1h[2*BNE], g_o1l[2*BNE];
__device__ __nv_bfloat16 g_ffh[2*BNF], g_ffl[2*BNF];
__device__ __nv_bfloat16 g_wqh[10*65536],  g_wql[10*65536];
__device__ __nv_bfloat16 g_wkh[10*65536],  g_wkl[10*65536];
__device__ __nv_bfloat16 g_wvh[10*65536],  g_wvl[10*65536];
__device__ __nv_bfloat16 g_wch[10*65536],  g_wcl[10*65536];
__device__ __nv_bfloat16 g_w1h[10*131072], g_w1l[10*131072];
__device__ __nv_bfloat16 g_w2h[10*131072], g_w2l[10*131072];

#if defined(__CUDA_ARCH__) && (__CUDA_ARCH__ >= 900)
#define PDL_SYNC()    cudaGridDependencySynchronize()
#define PDL_TRIGGER() cudaTriggerProgrammaticLaunchCompletion()
#else
#define PDL_SYNC()
#define PDL_TRIGGER()
#endif

// ================= fused setup kernel 1 =================
// blocks: [0,32) minmax | [32,52) ab | [52,148) vec0a | [148,5268) tsplit
__global__ void k_setup1(const float* __restrict__ data,
                         const float* __restrict__ Wedge, const float* __restrict__ bedge,
                         const float* __restrict__ Wmix,
                         const float* __restrict__ Wnode, const float* __restrict__ bnode,
                         const float* __restrict__ Wq, const float* __restrict__ Wk,
                         const float* __restrict__ Wv, const float* __restrict__ Wc,
                         const float* __restrict__ W1, const float* __restrict__ W2)
{
    PDL_SYNC();
    int bid = blockIdx.x;
    int tid = threadIdx.y*32 + threadIdx.x;

    if (bid < 32){
        // ---- minmax ----
        int b = bid >> 3, seg = bid & 7;
        const float* p = data + (size_t)b*Nn*Nn + seg*8192;
        float lmn = 1e30f, lmx = -1e30f;
        #pragma unroll
        for (int i = 0; i < 32; i++){ float v = p[tid + i*256]; lmn = fminf(lmn,v); lmx = fmaxf(lmx,v); }
        __shared__ float smn[256], smx[256];
        smn[tid]=lmn; smx[tid]=lmx; __syncthreads();
        for (int s=128; s; s>>=1){ if (tid<s){ smn[tid]=fminf(smn[tid],smn[tid+s]); smx[tid]=fmaxf(smx[tid],smx[tid+s]); } __syncthreads(); }
        if (!tid){ g_mnp[bid]=smn[0]; g_mxp[bid]=smx[0]; }
        return;
    }
    if (bid < 52){
        // ---- alpha/beta: block (ij, hhalf); warp w -> h = hhalf*8 + w ----
        int u = bid - 32;
        int ij = u >> 1, hh = u & 1;
        int w = tid >> 5, lane = tid & 31;
        int h = hh*8 + w;
        float a = 0.f, bb = 0.f;
        for (int e = lane; e < Ee; e += 32){
            float wm = Wmix[((size_t)ij*Ee + e)*Hh + h];
            a  += Wedge[e]*wm;
            bb += bedge[e]*wm;
        }
        for (int o=16;o;o>>=1){ a += __shfl_xor_sync(0xffffffffu,a,o); bb += __shfl_xor_sync(0xffffffffu,bb,o); }
        if (!lane){ g_alpha[ij*Hh+h]=a; g_beta[ij*Hh+h]=bb; }
        return;
    }
    if (bid < 148){
        // ---- vec0a: u in [0,96): idx=u>>4 (mat*2+z), seg=u&15 ----
        int u = bid - 52;
        int idx = u >> 4, seg = u & 15, j = tid;
        int mat = idx >> 1, z = idx & 1;
        const float* W = (mat==0 ? Wq : mat==1 ? Wk : Wv) + (size_t)z*Ee*256 + (size_t)seg*16*256 + j;
        int e0 = seg*16;
        float uu = 0.f, vv = 0.f;
        #pragma unroll
        for (int e = 0; e < 16; e++){
            float w = W[e*256];
            uu = fmaf(Wnode[e0+e], w, uu);
            vv = fmaf(bnode[e0+e], w, vv);
        }
        g_p0u[(idx*16 + seg)*256 + j] = uu;
        g_p0v[(idx*16 + seg)*256 + j] = vv;
        return;
    }
    // ---- tsplit ----
    {
        int tb = bid - 148;
        const float* s; __nv_bfloat16 *oh, *ol;
        int K, N, n0, k0, mat;
        if (tb < 2560){
            int type = tb / 640, loc = tb - type*640;
            mat = loc >> 6; int tile = loc & 63;
            if (type < 3 && mat < 2) return;          // layer-0 Wq/Wk/Wv unused
            K = 256; N = 256;
            n0 = (tile & 7)*32; k0 = (tile >> 3)*32;
            s  = (type==0?Wq:type==1?Wk:type==2?Wv:Wc);
            oh = (type==0?g_wqh:type==1?g_wkh:type==2?g_wvh:g_wch);
            ol = (type==0?g_wql:type==1?g_wkl:type==2?g_wvl:g_wcl);
        } else if (tb < 3840){
            int loc = tb - 2560;
            mat = loc >> 7; int tile = loc & 127;
            K = 256; N = 512;
            n0 = (tile & 15)*32; k0 = (tile >> 4)*32;
            s = W1; oh = g_w1h; ol = g_w1l;
        } else {
            int loc = tb - 3840;
            mat = loc >> 7; int tile = loc & 127;
            K = 512; N = 256;
            n0 = (tile & 7)*32; k0 = (tile >> 3)*32;
            s = W2; oh = g_w2h; ol = g_w2l;
        }
        s  += (size_t)mat*K*N;
        oh += (size_t)mat*K*N;
        ol += (size_t)mat*K*N;
        __shared__ float ts[32][33];
        int tx = threadIdx.x, ty = threadIdx.y;
        #pragma unroll
        for (int i=0;i<4;i++) ts[ty+i*8][tx] = s[(size_t)(k0+ty+i*8)*N + n0+tx];
        __syncthreads();
        #pragma unroll
        for (int i=0;i<4;i++){
            int n = n0+ty+i*8, k = k0+tx;
            float v = ts[tx][ty+i*8];
            __nv_bfloat16 hi = __float2bfloat16(v);
            oh[(size_t)n*K + k] = hi;
            ol[(size_t)n*K + k] = __float2bfloat16(v - __bfloat162float(hi));
        }
    }
}

// ================= fused setup kernel 2: scale(256) + vec0b(6) =================
__global__ void k_setup2(const float* __restrict__ data)
{
    PDL_SYNC();
    int bid = blockIdx.x;
    if (bid < 256){
        int x = bid & 7, y = (bid >> 3) & 7, b = bid >> 6;
        float m0v = 1e30f, M = -1e30f;
        #pragma unroll
        for (int j = 0; j < 8; j++){
            m0v = fminf(m0v, g_mnp[b*8+j]);
            M   = fmaxf(M,   g_mxp[b*8+j]);
        }
        float r = M - m0v; if (r == 0.f) r = 1.f;
        float inv = 1.f/r;
        __shared__ float tile[32][33];
        int n0 = y*32, mm0 = x*32;
        int tx = threadIdx.x, ty0 = threadIdx.y;
        #pragma unroll
        for (int i=0;i<4;i++){
            int ty = ty0 + i*8;
            float v = (data[((size_t)b*Nn + n0+ty)*Nn + mm0+tx] - m0v)*inv;
            g_scaled[((size_t)b*Nn + n0+ty)*Nn + mm0+tx] = v;
            tile[ty][tx] = v;
        }
        __syncthreads();
        #pragma unroll
        for (int i=0;i<4;i++){
            int ty = ty0 + i*8;
            g_scaledT[((size_t)b*Nn + mm0+ty)*Nn + n0+tx] = tile[tx][ty];
        }
        return;
    }
    {   // vec0b
        int idx = bid - 256, j = threadIdx.y*32 + threadIdx.x;
        float u = 0.f, v = 0.f;
        #pragma unroll
        for (int s = 0; s < 16; s++){
            u += g_p0u[(idx*16 + s)*256 + j];
            v += g_p0v[(idx*16 + s)*256 + j];
        }
        g_qkv0u[idx*256 + j] = u;
        g_qkv0v[idx*256 + j] = v;
    }
}

// emb + direct layer-0 Q/K/V (rank-1)
__global__ void k_emb(const float* __restrict__ nr, const float* __restrict__ Wn,
                      const float* __restrict__ bn)
{
    PDL_SYNC();
    int idx = blockIdx.x*256 + threadIdx.x;
    int e = idx & (Ee-1), bni = idx >> 8;
    float r = nr[bni];
    float v = r*Wn[e] + bn[e];
    g_bufA[idx] = v; g_bufA[idx + BNE] = v;
    #pragma unroll
    for (int z = 0; z < 2; z++){
        g_Q[(size_t)z*BNE + idx] = fmaf(r, g_qkv0u[(0*2+z)*256 + e], g_qkv0v[(0*2+z)*256 + e]);
        g_K[(size_t)z*BNE + idx] = fmaf(r, g_qkv0u[(1*2+z)*256 + e], g_qkv0v[(1*2+z)*256 + e]);
        g_V[(size_t)z*BNE + idx] = fmaf(r, g_qkv0u[(2*2+z)*256 + e], g_qkv0v[(2*2+z)*256 + e]);
    }
    PDL_TRIGGER();
}

// ================= HMMA 3xBF16 GEMM core, 2-stage cp.async =================
__device__ __forceinline__ void cp16(uint32_t dst, const void* src){
    asm volatile("cp.async.cg.shared.global [%0], [%1], 16;\n" :: "r"(dst), "l"(src));
}
__device__ __forceinline__ void hmma(float* c, const uint32_t* a, const uint32_t* b){
    asm volatile("mma.sync.aligned.m16n8k16.row.col.f32.bf16.bf16.f32 "
        "{%0,%1,%2,%3}, {%4,%5,%6,%7}, {%8,%9}, {%0,%1,%2,%3};"
        : "+f"(c[0]), "+f"(c[1]), "+f"(c[2]), "+f"(c[3])
        : "r"(a[0]), "r"(a[1]), "r"(a[2]), "r"(a[3]), "r"(b[0]), "r"(b[1]));
}

__device__ __forceinline__ void tgemm_core(
    const __nv_bfloat16* __restrict__ ah, const __nv_bfloat16* __restrict__ al,
    const __nv_bfloat16* __restrict__ wh, const __nv_bfloat16* __restrict__ wl,
    const float* __restrict__ bias, const float* __restrict__ res,
    float* __restrict__ Cf, __nv_bfloat16* __restrict__ Chi, __nv_bfloat16* __restrict__ Clo,
    int m0, int n0, int Ng, int K, int relu)
{
    __shared__ __align__(16) __nv_bfloat16 smb[2][4][64*40];
    int tid = threadIdx.x;
    int lane = tid & 31, w = tid >> 5;
    int wm = (w >> 1)*32, wn = (w & 1)*32;
    int g = lane >> 2, tg = lane & 3;
    uint32_t sbase;
    asm("{ .reg .u64 t; cvta.to.shared.u64 t, %1; cvt.u32.u64 %0, t; }"
        : "=r"(sbase) : "l"((void*)&smb[0][0][0]));

    float acc[2][4][4];
    #pragma unroll
    for (int mi=0;mi<2;mi++)
        #pragma unroll
        for (int ni=0;ni<4;ni++)
            #pragma unroll
            for (int q=0;q<4;q++) acc[mi][ni][q]=0.f;

    const int nch = K >> 5;
    int crow = tid >> 2, cseg = (tid & 3)*8;

    auto issue = [&](int c){
        uint32_t sb2 = sbase + (uint32_t)((c & 1) ? 20480 : 0);
        int co = c*32 + cseg;
        #pragma unroll
        for (int it = 0; it < 2; it++){
            int row = crow + it*32;
            uint32_t dof = (uint32_t)((row*40 + cseg)*2);
            cp16(sb2         + dof, ah + (size_t)(m0+row)*K + co);
            cp16(sb2 + 5120  + dof, al + (size_t)(m0+row)*K + co);
            cp16(sb2 + 10240 + dof, wh + (size_t)(n0+row)*K + co);
            cp16(sb2 + 15360 + dof, wl + (size_t)(n0+row)*K + co);
        }
        asm volatile("cp.async.commit_group;\n");
    };

    issue(0);
    for (int c = 0; c < nch; c++){
        asm volatile("cp.async.wait_group 0;\n");
        __syncthreads();
        if (c + 1 < nch) issue(c + 1);
        int st = c & 1;
        const __nv_bfloat16* pA0 = &smb[st][0][0];
        const __nv_bfloat16* pA1 = &smb[st][1][0];
        const __nv_bfloat16* pB0 = &smb[st][2][0];
        const __nv_bfloat16* pB1 = &smb[st][3][0];
        #pragma unroll
        for (int ks = 0; ks < 2; ks++){
            int kb = ks*16 + 2*tg;
            uint32_t fah[2][4], fal[2][4];
            #pragma unroll
            for (int mi = 0; mi < 2; mi++){
                int rb = wm + mi*16 + g;
                fah[mi][0] = *(const uint32_t*)&pA0[rb*40 + kb];
                fah[mi][1] = *(const uint32_t*)&pA0[(rb+8)*40 + kb];
                fah[mi][2] = *(const uint32_t*)&pA0[rb*40 + kb + 8];
                fah[mi][3] = *(const uint32_t*)&pA0[(rb+8)*40 + kb + 8];
                fal[mi][0] = *(const uint32_t*)&pA1[rb*40 + kb];
                fal[mi][1] = *(const uint32_t*)&pA1[(rb+8)*40 + kb];
                fal[mi][2] = *(const uint32_t*)&pA1[rb*40 + kb + 8];
                fal[mi][3] = *(const uint32_t*)&pA1[(rb+8)*40 + kb + 8];
            }
            uint32_t fbh[4][2], fbl[4][2];
            #pragma unroll
            for (int ni = 0; ni < 4; ni++){
                int nb = wn + ni*8 + g;
                fbh[ni][0] = *(const uint32_t*)&pB0[nb*40 + kb];
                fbh[ni][1] = *(const uint32_t*)&pB0[nb*40 + kb + 8];
                fbl[ni][0] = *(const uint32_t*)&pB1[nb*40 + kb];
                fbl[ni][1] = *(const uint32_t*)&pB1[nb*40 + kb + 8];
            }
            #pragma unroll
            for (int mi = 0; mi < 2; mi++)
                #pragma unroll
                for (int ni = 0; ni < 4; ni++){
                    hmma(acc[mi][ni], fah[mi], fbh[ni]);
                    hmma(acc[mi][ni], fah[mi], fbl[ni]);
                    hmma(acc[mi][ni], fal[mi], fbh[ni]);
                }
        }
    }

    PDL_TRIGGER();
    #pragma unroll
    for (int mi = 0; mi < 2; mi++){
        #pragma unroll
        for (int ni = 0; ni < 4; ni++){
            int col = n0 + wn + ni*8 + 2*tg;
            float b0 = bias ? bias[col]   : 0.f;
            float b1 = bias ? bias[col+1] : 0.f;
            #pragma unroll
            for (int half = 0; half < 2; half++){
                int m = m0 + wm + mi*16 + g + half*8;
                float v0 = acc[mi][ni][half*2+0] + b0;
                float v1 = acc[mi][ni][half*2+1] + b1;
                if (res){
                    v0 += res[(size_t)m*Ng + col];
                    v1 += res[(size_t)m*Ng + col+1];
                }
                if (relu){ v0 = fmaxf(v0, 0.f); v1 = fmaxf(v1, 0.f); }
                if (Cf){
                    float2 o; o.x = v0; o.y = v1;
                    *(float2*)&Cf[(size_t)m*Ng + col] = o;
                }
                if (Chi){
                    __nv_bfloat16 h0 = __float2bfloat16(v0), h1 = __float2bfloat16(v1);
                    __nv_bfloat162 hp; hp.x = h0; hp.y = h1;
                    __nv_bfloat162 lp;
                    lp.x = __float2bfloat16(v0 - __bfloat162float(h0));
                    lp.y = __float2bfloat16(v1 - __bfloat162float(h1));
                    *(__nv_bfloat162*)&Chi[(size_t)m*Ng + col] = hp;
                    *(__nv_bfloat162*)&Clo[(size_t)m*Ng + col] = lp;
                }
            }
        }
    }
}

// fused QKV: grid (12, 16, 2)
__global__ void __launch_bounds__(128) k_tqkv(
                       const __nv_bfloat16* __restrict__ xh, const __nv_bfloat16* __restrict__ xl,
                       const __nv_bfloat16* wqh, const __nv_bfloat16* wql,
                       const __nv_bfloat16* wkh, const __nv_bfloat16* wkl,
                       const __nv_bfloat16* wvh, const __nv_bfloat16* wvl,
                       float* Q, float* K, float* V)
{
    PDL_SYNC();
    int wsel = blockIdx.x >> 2, nt = blockIdx.x & 3, z = blockIdx.z;
    int az = wsel ? (1 - z) : z;
    const __nv_bfloat16 *wh, *wl; float* out;
    if (wsel == 0){ wh = wqh; wl = wql; out = Q; }
    else if (wsel == 1){ wh = wkh; wl = wkl; out = K; }
    else { wh = wvh; wl = wvl; out = V; }
    tgemm_core(xh + (size_t)az*BNE, xl + (size_t)az*BNE,
               wh + (size_t)z*65536, wl + (size_t)z*65536,
               nullptr, nullptr,
               out + (size_t)z*BNE, nullptr, nullptr,
               blockIdx.y*64, nt*64, 256, 256, 0);
}

__global__ void __launch_bounds__(128) k_tgemm(
                        const __nv_bfloat16* __restrict__ ah, const __nv_bfloat16* __restrict__ al, int aStrideZ,
                        const __nv_bfloat16* __restrict__ wh, const __nv_bfloat16* __restrict__ wl, int wStrideZ,
                        const float* bias, int biasStrideZ,
                        const float* res, int resStrideZ,
                        float* Cf, __nv_bfloat16* Chi, __nv_bfloat16* Clo, int cStrideZ,
                        int Ng, int K, int relu)
{
    PDL_SYNC();
    int z = blockIdx.z;
    tgemm_core(ah + (size_t)z*aStrideZ, al + (size_t)z*aStrideZ,
               wh + (size_t)z*wStrideZ, wl + (size_t)z*wStrideZ,
               bias ? bias + (size_t)z*biasStrideZ : nullptr,
               res  ? res  + (size_t)z*resStrideZ  : nullptr,
               Cf  ? Cf  + (size_t)z*cStrideZ : nullptr,
               Chi ? Chi + (size_t)z*cStrideZ : nullptr,
               Clo ? Clo + (size_t)z*cStrideZ : nullptr,
               blockIdx.y*64, blockIdx.x*64, Ng, K, relu);
}

// ================= fused attention: 4 row-groups per block =================
// grid (2, 64, 2), 256 threads; K/V staged once, four 32-row passes.
__global__ void __launch_bounds__(256) k_attn(
    const float* __restrict__ Q, const float* __restrict__ Kg, const float* __restrict__ Vg,
    const float* __restrict__ scaled, const float* __restrict__ scaledT,
    const float* __restrict__ alpha, const float* __restrict__ beta,
    __nv_bfloat16* __restrict__ Oh, __nv_bfloat16* __restrict__ Ol)
{
    PDL_SYNC();
    __shared__ float qs[32][17];
    __shared__ float Vs[256][17];
    __shared__ float Ks[256][17];
    __shared__ float red[4][545];
    __shared__ float sminv[32];

    int rgp = blockIdx.x, bh = blockIdx.y, z = blockIdx.z;
    int b = bh >> 4, h = bh & 15;
    const float* Sc = z ? scaledT : scaled;
    size_t base = ((size_t)(z*Bb+b))*(size_t)Nn*Ee;
    const float* Kp = Kg + base + h*16;
    const float* Vp = Vg + base + h*16;
    float al = alpha[z*Hh+h], be = beta[z*Hh+h];
    int tid = threadIdx.x;

    {
        int m = tid, sh = m >> 4;
        const float4* kr4 = (const float4*)(Kp + (size_t)m*Ee);
        const float4* vr4 = (const float4*)(Vp + (size_t)m*Ee);
        #pragma unroll
        for (int j4 = 0; j4 < 4; j4++){
            float4 kv = kr4[j4], vv = vr4[j4];
            Ks[m][(j4*4+0+sh)&15] = kv.x;
            Ks[m][(j4*4+1+sh)&15] = kv.y;
            Ks[m][(j4*4+2+sh)&15] = kv.z;
            Ks[m][(j4*4+3+sh)&15] = kv.w;
            Vs[m][(j4*4+0+sh)&15] = vv.x;
            Vs[m][(j4*4+1+sh)&15] = vv.y;
            Vs[m][(j4*4+2+sh)&15] = vv.z;
            Vs[m][(j4*4+3+sh)&15] = vv.w;
        }
    }

    int n2 = tid >> 4, s16 = tid & 15, m0 = s16*16;

    for (int pass = 0; pass < 4; pass++){
        int rg = rgp*4 + pass;
        __syncthreads();
        {
            int r = tid >> 3, dq = (tid & 7)*2;
            const float* Qp = Q + base + (size_t)(rg*32 + r)*Ee + h*16;
            float2 q2 = *(const float2*)(Qp + dq);
            qs[r][dq]   = q2.x*0.25f;
            qs[r][dq+1] = q2.y*0.25f;
        }
        __syncthreads();

        float q0[16], q1[16];
        #pragma unroll
        for (int d = 0; d < 16; d++){ q0[d] = qs[n2][d]; q1[d] = qs[n2+16][d]; }

        float acc0[16], acc1[16];
        {
            const float* sr0 = Sc + ((size_t)b*Nn + rg*32 + n2)*Nn + m0;
            const float* sr1 = sr0 + (size_t)16*Nn;
            #pragma unroll
            for (int j = 0; j < 16; j += 4){
                float4 v0 = *(const float4*)&sr0[j];
                acc0[j]   = fmaf(v0.x, al, be); acc0[j+1] = fmaf(v0.y, al, be);
                acc0[j+2] = fmaf(v0.z, al, be); acc0[j+3] = fmaf(v0.w, al, be);
                float4 v1 = *(const float4*)&sr1[j];
                acc1[j]   = fmaf(v1.x, al, be); acc1[j+1] = fmaf(v1.y, al, be);
                acc1[j+2] = fmaf(v1.z, al, be); acc1[j+3] = fmaf(v1.w, al, be);
            }
        }
        #pragma unroll
        for (int j = 0; j < 16; j++){
            const float* kr = &Ks[m0+j][0];
            float a0 = acc0[j], a1 = acc1[j];
            #pragma unroll
            for (int d = 0; d < 16; d++){
                float kv = kr[(d+s16)&15];
                a0 = fmaf(q0[d], kv, a0);
                a1 = fmaf(q1[d], kv, a1);
            }
            acc0[j] = a0; acc1[j] = a1;
        }

        float mx0 = -1e30f, mx1 = -1e30f;
        #pragma unroll
        for (int j = 0; j < 16; j++){ mx0 = fmaxf(mx0, acc0[j]); mx1 = fmaxf(mx1, acc1[j]); }
        #pragma unroll
        for (int o = 1; o < 16; o <<= 1){
            mx0 = fmaxf(mx0, __shfl_xor_sync(0xffffffffu, mx0, o));
            mx1 = fmaxf(mx1, __shfl_xor_sync(0xffffffffu, mx1, o));
        }
        float sm0 = 0.f, sm1 = 0.f;
        #pragma unroll
        for (int j = 0; j < 16; j++){
            acc0[j] = __expf(acc0[j]-mx0); sm0 += acc0[j];
            acc1[j] = __expf(acc1[j]-mx1); sm1 += acc1[j];
        }
        #pragma unroll
        for (int o = 1; o < 16; o <<= 1){
            sm0 += __shfl_xor_sync(0xffffffffu, sm0, o);
            sm1 += __shfl_xor_sync(0xffffffffu, sm1, o);
        }
        if (s16 == 0){ sminv[n2] = 1.f/sm0; sminv[n2+16] = 1.f/sm1; }

        float p0[16], p1[16];
        #pragma unroll
        for (int d = 0; d < 16; d++){ p0[d] = 0.f; p1[d] = 0.f; }
        #pragma unroll
        for (int j = 0; j < 16; j++){
            const float* vr = &Vs[m0+j][0];
            float e0 = acc0[j], e1 = acc1[j];
            #pragma unroll
            for (int d = 0; d < 16; d++){
                float vv = vr[(d+s16)&15];
                p0[d] = fmaf(e0, vv, p0[d]);
                p1[d] = fmaf(e1, vv, p1[d]);
            }
        }
        #pragma unroll
        for (int d = 0; d < 16; d++){
            p0[d] += __shfl_xor_sync(0xffffffffu, p0[d], 8);
            p1[d] += __shfl_xor_sync(0xffffffffu, p1[d], 8);
            p0[d] += __shfl_xor_sync(0xffffffffu, p0[d], 4);
            p1[d] += __shfl_xor_sync(0xffffffffu, p1[d], 4);
        }
        if (s16 < 4){
            #pragma unroll
            for (int d = 0; d < 16; d++){
                red[s16][n2*17 + d]      = p0[d];
                red[s16][(n2+16)*17 + d] = p1[d];
            }
        }
        __syncthreads();

        if (pass == 3){ PDL_TRIGGER(); }
        {
            int r = tid >> 3, dp = (tid & 7)*2;
            float s0 = 0.f, s1 = 0.f;
            #pragma unroll
            for (int s = 0; s < 4; s++){
                s0 += red[s][r*17 + dp];
                s1 += red[s][r*17 + dp + 1];
            }
            float iv = sminv[r];
            float v0 = s0*iv, v1 = s1*iv;
            size_t off = base + (size_t)(rg*32 + r)*Ee + h*16 + dp;
            __nv_bfloat16 h0 = __float2bfloat16(v0), h1 = __float2bfloat16(v1);
            __nv_bfloat162 hp; hp.x = h0; hp.y = h1;
            __nv_bfloat162 lp;
            lp.x = __float2bfloat16(v0 - __bfloat162float(h0));
            lp.y = __float2bfloat16(v1 - __bfloat162float(h1));
            *(__nv_bfloat162*)&Oh[off] = hp;
            *(__nv_bfloat162*)&Ol[off] = lp;
        }
    }
}

// instance norm + optional bf16 split; grid (Bb, 16, 2), 256 thr
__global__ void __launch_bounds__(256) k_inorm(
                        const float* __restrict__ X, float* __restrict__ Y,
                        const float* __restrict__ wbase, const float* __restrict__ bbase,
                        __nv_bfloat16* __restrict__ Yh, __nv_bfloat16* __restrict__ Yl)
{
    PDL_SYNC();
    int z = blockIdx.z, b = blockIdx.x, e0 = blockIdx.y*16;
    const float* w = wbase + (size_t)z*Ee;
    const float* bp = bbase + (size_t)z*Ee;
    int tid = threadIdx.x;
    int el = tid & 15, nc = tid >> 4;
    size_t base = ((size_t)(z*Bb+b))*Nn*Ee;
    float vals[16];
    float s = 0.f, ss = 0.f;
    #pragma unroll
    for (int k = 0; k < 16; k++){
        float v = X[base + (size_t)(nc + 16*k)*Ee + e0 + el];
        vals[k] = v;
        s += v; ss += v*v;
    }
    __shared__ float shs[16][17], shss[16][17];
    __shared__ float muA[16], invA[16];
    shs[nc][el] = s; shss[nc][el] = ss;
    __syncthreads();
    if (tid < 16){
        float S = 0.f, SS = 0.f;
        #pragma unroll
        for (int j = 0; j < 16; j++){ S += shs[j][tid]; SS += shss[j][tid]; }
        float mu = S*(1.f/Nn);
        float var = SS*(1.f/Nn) - mu*mu;
        muA[tid] = mu;
        invA[tid] = rsqrtf(var + 1e-5f);
    }
    __syncthreads();
    float mu = muA[el];
    float sc = invA[el]*w[e0+el];
    float sb = bp[e0+el];
    PDL_TRIGGER();
    #pragma unroll
    for (int k = 0; k < 16; k++){
        size_t off = base + (size_t)(nc + 16*k)*Ee + e0 + el;
        float y = (vals[k]-mu)*sc + sb;
        Y[off] = y;
        if (Yh){
            __nv_bfloat16 hi = __float2bfloat16(y);
            Yh[off] = hi;
            Yl[off] = __float2bfloat16(y - __bfloat162float(hi));
        }
    }
}

// ================= host launcher =================
template <typename F, typename... A>
static inline void pdl_launch(F f, dim3 grid, dim3 block, A... args)
{
    cudaLaunchConfig_t cfg = {};
    cfg.gridDim = grid; cfg.blockDim = block;
    cfg.dynamicSmemBytes = 0; cfg.stream = 0;
    cudaLaunchAttribute at[1];
    at[0].id = cudaLaunchAttributeProgrammaticStreamSerialization;
    at[0].val.programmaticStreamSerializationAllowed = 1;
    cfg.attrs = at; cfg.numAttrs = 1;
    if (cudaLaunchKernelEx(&cfg, f, args...) != cudaSuccess)
        f<<<grid, block>>>(args...);
}

extern "C" void kernel_launch(void* const* d_in, const int* in_sizes, int n_in,
                              void* d_out, int out_size)
{
    const float* data      = (const float*)d_in[0];
    const float* node_rand = (const float*)d_in[1];
    const float* Wnode = (const float*)d_in[2];
    const float* bnode = (const float*)d_in[3];
    const float* Wedge = (const float*)d_in[4];
    const float* bedge = (const float*)d_in[5];
    const float* Wq    = (const float*)d_in[6];
    const float* Wk    = (const float*)d_in[7];
    const float* Wv    = (const float*)d_in[8];
    const float* Wcomb = (const float*)d_in[9];
    const float* bcomb = (const float*)d_in[10];
    const float* n1w   = (const float*)d_in[11];
    const float* n1b   = (const float*)d_in[12];
    const float* W1    = (const float*)d_in[13];
    const float* b1    = (const float*)d_in[14];
    const float* W2    = (const float*)d_in[15];
    const float* b2    = (const float*)d_in[16];
    const float* n2w   = (const float*)d_in[17];
    const float* n2b   = (const float*)d_in[18];
    const float* Wmix  = (const float*)d_in[19];

    float *scaled, *scaledT, *alpha, *beta;
    float *bufA, *bufB, *Qb, *Kb, *Vb, *t1, *o1;
    __nv_bfloat16 *xhA,*xlA,*xhB,*xlB,*oh,*ol,*o1h,*o1l,*ffh,*ffl;
    __nv_bfloat16 *wqh,*wql,*wkh,*wkl,*wvh,*wvl,*wch,*wcl,*w1h,*w1l,*w2h,*w2l;
    cudaGetSymbolAddress((void**)&scaled,  g_scaled);
    cudaGetSymbolAddress((void**)&scaledT, g_scaledT);
    cudaGetSymbolAddress((void**)&alpha,   g_alpha);
    cudaGetSymbolAddress((void**)&beta,    g_beta);
    cudaGetSymbolAddress((void**)&bufA,    g_bufA);
    cudaGetSymbolAddress((void**)&bufB,    g_bufB);
    cudaGetSymbolAddress((void**)&Qb,      g_Q);
    cudaGetSymbolAddress((void**)&Kb,      g_K);
    cudaGetSymbolAddress((void**)&Vb,      g_V);
    cudaGetSymbolAddress((void**)&t1,      g_t1);
    cudaGetSymbolAddress((void**)&o1,      g_o1);
    cudaGetSymbolAddress((void**)&xhA, g_xhA); cudaGetSymbolAddress((void**)&xlA, g_xlA);
    cudaGetSymbolAddress((void**)&xhB, g_xhB); cudaGetSymbolAddress((void**)&xlB, g_xlB);
    cudaGetSymbolAddress((void**)&oh,  g_oh);  cudaGetSymbolAddress((void**)&ol,  g_ol);
    cudaGetSymbolAddress((void**)&o1h, g_o1h); cudaGetSymbolAddress((void**)&o1l, g_o1l);
    cudaGetSymbolAddress((void**)&ffh, g_ffh); cudaGetSymbolAddress((void**)&ffl, g_ffl);
    cudaGetSymbolAddress((void**)&wqh, g_wqh); cudaGetSymbolAddress((void**)&wql, g_wql);
    cudaGetSymbolAddress((void**)&wkh, g_wkh); cudaGetSymbolAddress((void**)&wkl, g_wkl);
    cudaGetSymbolAddress((void**)&wvh, g_wvh); cudaGetSymbolAddress((void**)&wvl, g_wvl);
    cudaGetSymbolAddress((void**)&wch, g_wch); cudaGetSymbolAddress((void**)&wcl, g_wcl);
    cudaGetSymbolAddress((void**)&w1h, g_w1h); cudaGetSymbolAddress((void**)&w1l, g_w1l);
    cudaGetSymbolAddress((void**)&w2h, g_w2h); cudaGetSymbolAddress((void**)&w2l, g_w2l);

    // setup: 3 launches
    pdl_launch(k_setup1, dim3(5268), dim3(32,8), data, Wedge, bedge, Wmix,
               Wnode, bnode, Wq, Wk, Wv, Wcomb, W1, W2);
    pdl_launch(k_setup2, dim3(262), dim3(32,8), data);
    pdl_launch(k_emb, dim3(BNE/256), dim3(256), node_rand, Wnode, bnode);

    for (int i = 0; i < Ll; i++){
        const float* Xc = (i & 1) ? bufB : bufA;
        __nv_bfloat16* xhc = (i & 1) ? xhB : xhA;
        __nv_bfloat16* xlc = (i & 1) ? xlB : xlA;
        __nv_bfloat16* xhn = (i & 1) ? xhA : xhB;
        __nv_bfloat16* xln = (i & 1) ? xlA : xlB;
        int last = (i == Ll-1);
        float* Xn = last ? (float*)d_out : ((i & 1) ? bufA : bufB);
        size_t w256 = (size_t)i*2*65536;
        size_t w512 = (size_t)i*2*131072;
        const float* bcomb_i = bcomb + (size_t)i*2*Ee;
        const float* b1_i    = b1    + (size_t)i*2*FFh;
        const float* b2_i    = b2    + (size_t)i*2*Ee;

        if (i > 0){   // layer 0 Q/K/V produced directly by k_emb (rank-1)
            pdl_launch(k_tqkv, dim3(12,16,2), dim3(128),
                (const __nv_bfloat16*)xhc, (const __nv_bfloat16*)xlc,
                (const __nv_bfloat16*)(wqh + w256), (const __nv_bfloat16*)(wql + w256),
                (const __nv_bfloat16*)(wkh + w256), (const __nv_bfloat16*)(wkl + w256),
                (const __nv_bfloat16*)(wvh + w256), (const __nv_bfloat16*)(wvl + w256),
                Qb, Kb, Vb);
        }
        pdl_launch(k_attn, dim3(2, Bb*Hh, 2), dim3(256),
            (const float*)Qb, (const float*)Kb, (const float*)Vb,
            (const float*)scaled, (const float*)scaledT,
            (const float*)(alpha + i*2*Hh), (const float*)(beta + i*2*Hh), oh, ol);
        pdl_launch(k_tgemm, dim3(4,16,2), dim3(128),
            (const __nv_bfloat16*)oh, (const __nv_bfloat16*)ol, (int)BNE,
            (const __nv_bfloat16*)(wch + w256), (const __nv_bfloat16*)(wcl + w256), (int)65536,
            bcomb_i, (int)Ee, (const float*)Xc, (int)BNE,
            t1, (__nv_bfloat16*)nullptr, (__nv_bfloat16*)nullptr, (int)BNE, (int)256, (int)256, (int)0);
        pdl_launch(k_inorm, dim3(Bb,16,2), dim3(256),
            (const float*)t1, o1, n1w + (size_t)i*2*Ee, n1b + (size_t)i*2*Ee, o1h, o1l);
        pdl_launch(k_tgemm, dim3(8,16,2), dim3(128),
            (const __nv_bfloat16*)o1h, (const __nv_bfloat16*)o1l, (int)BNE,
            (const __nv_bfloat16*)(w1h + w512), (const __nv_bfloat16*)(w1l + w512), (int)131072,
            b1_i, (int)FFh, (const float*)nullptr, (int)0,
            (float*)nullptr, ffh, ffl, (int)BNF, (int)512, (int)256, (int)1);
        pdl_launch(k_tgemm, dim3(4,16,2), dim3(128),
            (const __nv_bfloat16*)ffh, (const __nv_bfloat16*)ffl, (int)BNF,
            (const __nv_bfloat16*)(w2h + w512), (const __nv_bfloat16*)(w2l + w512), (int)131072,
            b2_i, (int)Ee, (const float*)o1, (int)BNE,
            t1, (__nv_bfloat16*)nullptr, (__nv_bfloat16*)nullptr, (int)BNE, (int)256, (int)512, (int)0);
        pdl_launch(k_inorm, dim3(Bb,16,2), dim3(256),
            (const float*)t1, Xn, n2w + (size_t)i*2*Ee, n2b + (size_t)i*2*Ee,
            last ? (__nv_bfloat16*)nullptr : xhn, last ? (__nv_bfloat16*)nullptr : xln);
    }
}